// round 13
// baseline (speedup 1.0000x reference)
#include <cuda_runtime.h>
#include <math.h>

#define NB   16
#define NI   127
#define NN   16129      // 127*127
#define IMG  65536      // 256*256
#define TS   32
#define JHL  22
#define JLT  76         // TS + 2*JHL
#define JLN  5776       // JLT*JLT

typedef unsigned long long u64;

// ---------------- scratch (static device globals) ----------------------------
static __device__ float  g_x[NB * NN];
static __device__ float  g_r[NB * NN];
static __device__ float2 g_FA[NB * IMG];
static __device__ float2 g_FB[NB * IMG];   // also reused as float (real) buffer
static __device__ float2 g_Kc[NB * 98];    // composed 7x7 kernels: [49 fwd | 49 adj]
static __device__ float2 g_part[1024];

// ---------------- misc helpers ------------------------------------------------
__device__ __forceinline__ int get_K(const int* ep) {
    int ei = *ep;
    int e;
    if (ei > 0 && ei <= 1000000) {
        e = ei;
    } else {
        float ff = __int_as_float(ei);
        e = (ff >= 1.0f && ff <= 1000000.0f) ? (int)ff : 120;
    }
    int K = (e - 1) / 40 + 1;
    if (K > 10) K = 10;
    if (K < 1)  K = 1;
    return K;
}

// base-4 digit reversal of 8-bit index
__device__ __forceinline__ int dr4(int p) {
    return ((p & 3) << 6) | (((p >> 2) & 3) << 4) | (((p >> 4) & 3) << 2) | ((p >> 6) & 3);
}

__device__ __forceinline__ float2 cmulf(float2 a, float2 b) {
    return make_float2(a.x * b.x - a.y * b.y, a.x * b.y + a.y * b.x);
}

__device__ __forceinline__ void build_tw(float2* tw, int tid, float sign) {
    if (tid < 192) {
        float s, c;
        __sincosf(sign * 6.283185307179586f * (float)tid * (1.0f / 256.0f), &s, &c);
        tw[tid] = make_float2(c, s);
    }
}

// Radix-4 256-pt DIT FFT, input base-4 digit-reversed, output natural.
// One butterfly per call-site index i (0..63) per stage.
template <int STRIDE, int SGN>
__device__ __forceinline__ void r4_bfly(float2* s, const float2* tw, int i, int st) {
    int L    = 1 << (2 * st);
    int k    = i & (L - 1);
    int g    = i >> (2 * st);
    int i0   = g * 4 * L + k;
    int step = 64 >> (2 * st);
    float2 a = s[i0 * STRIDE];
    float2 b = s[(i0 + L) * STRIDE];
    float2 c = s[(i0 + 2 * L) * STRIDE];
    float2 d = s[(i0 + 3 * L) * STRIDE];
    b = cmulf(b, tw[k * step]);
    c = cmulf(c, tw[2 * k * step]);
    d = cmulf(d, tw[3 * k * step]);
    float2 t0 = make_float2(a.x + c.x, a.y + c.y);
    float2 t1 = make_float2(a.x - c.x, a.y - c.y);
    float2 t2 = make_float2(b.x + d.x, b.y + d.y);
    float2 t3 = make_float2(b.x - d.x, b.y - d.y);
    float2 rot = make_float2(-(float)SGN * t3.y, (float)SGN * t3.x);
    s[i0 * STRIDE]           = make_float2(t0.x + t2.x, t0.y + t2.y);
    s[(i0 + L) * STRIDE]     = make_float2(t1.x + rot.x, t1.y + rot.y);
    s[(i0 + 2 * L) * STRIDE] = make_float2(t0.x - t2.x, t0.y - t2.y);
    s[(i0 + 3 * L) * STRIDE] = make_float2(t1.x - rot.x, t1.y - rot.y);
}

// ---------------- kernels ----------------------------------------------------
// One-time: compose the 3-conv stacks into per-sample 7x7 correlation kernels.
__global__ void __launch_bounds__(64)
compose_kernels(const float* __restrict__ w1r, const float* __restrict__ w1i,
                const float* __restrict__ w2r, const float* __restrict__ w2i,
                const float* __restrict__ w3r, const float* __restrict__ w3i) {
    __shared__ float s1r[36], s1i[36], s2r[144], s2i[144], s3r[36], s3i[36];
    int b = blockIdx.x;
    int t = threadIdx.x;
    if (t < 36) { s1r[t] = w1r[b * 36 + t]; s1i[t] = w1i[b * 36 + t]; }
    if (t < 36) { s3r[t] = w3r[b * 36 + t]; s3i[t] = w3i[b * 36 + t]; }
    for (int i = t; i < 144; i += 64) { s2r[i] = w2r[b * 144 + i]; s2i[i] = w2i[b * 144 + i]; }
    __syncthreads();
    if (t >= 49) return;
    int my = t / 7 - 3, mx = t % 7 - 3;
    float fr = 0.f, fi = 0.f, ar = 0.f, ai = 0.f;
    for (int c2 = 0; c2 < 4; ++c2)
    for (int c1 = 0; c1 < 4; ++c1)
    for (int j = 0; j < 9; ++j) {
        int jy = j / 3 - 1, jx = j % 3 - 1;
        for (int k = 0; k < 9; ++k) {
            int ky = k / 3 - 1, kx = k % 3 - 1;
            int ly = my - jy - ky, lx = mx - jx - kx;
            if (ly < -1 || ly > 1 || lx < -1 || lx > 1) continue;
            int l = (ly + 1) * 3 + (lx + 1);
            {
                float xr = s3r[c2 * 9 + j],            xi = s3i[c2 * 9 + j];
                float yr = s2r[(c2 * 4 + c1) * 9 + k], yi = s2i[(c2 * 4 + c1) * 9 + k];
                float zr = s1r[c1 * 9 + l],            zi = s1i[c1 * 9 + l];
                float pr = xr * yr - xi * yi, pi = xr * yi + xi * yr;
                fr += pr * zr - pi * zi;
                fi += pr * zi + pi * zr;
            }
            {
                int jT = (j % 3) * 3 + j / 3;
                int kT = (k % 3) * 3 + k / 3;
                int lT = (l % 3) * 3 + l / 3;
                float xr = s1r[c2 * 9 + jT],            xi = -s1i[c2 * 9 + jT];
                float yr = s2r[(c1 * 4 + c2) * 9 + kT], yi = -s2i[(c1 * 4 + c2) * 9 + kT];
                float zr = s3r[c1 * 9 + lT],            zi = -s3i[c1 * 9 + lT];
                float pr = xr * yr - xi * yi, pi = xr * yi + xi * yr;
                ar += pr * zr - pi * zi;
                ai += pr * zi + pi * zr;
            }
        }
    }
    g_Kc[b * 98 + t]      = make_float2(fr, fi);
    g_Kc[b * 98 + 49 + t] = make_float2(ar, ai);
}

// Merged Jacobi: all 20 sweeps in one launch, 76x76 tiles (halo 22),
// 1024 threads, dynamic smem. Emits x and r = f - A x.
__global__ void __launch_bounds__(1024)
jacobi_tile(const float* __restrict__ f, const float* __restrict__ kA,
            const int* __restrict__ ep, int iter, int zero) {
    if (iter >= get_K(ep)) return;
    extern __shared__ float jsm[];
    float* xs0 = jsm;
    float* xs1 = jsm + JLN;
    float* fs  = jsm + 2 * JLN;
    int b  = blockIdx.z;
    int ox = blockIdx.x * TS - JHL;
    int oy = blockIdx.y * TS - JHL;
    int tid = threadIdx.x;
    const float* ka = kA + b * 9;
    float k0 = ka[0], k1 = ka[1], k2 = ka[2], k3 = ka[3], k4 = ka[4];
    float k5 = ka[5], k6 = ka[6], k7 = ka[7], k8 = ka[8];
    float tau = 0.5f / k4;

    int  iyk[6], ixk[6];
    bool okk[6], domk[6];
#pragma unroll
    for (int k = 0; k < 6; ++k) {
        int p = tid + k * 1024;
        bool ok = p < JLN;
        int iy = 0, ix = 0;
        if (ok) { iy = p / JLT; ix = p - iy * JLT; }
        int gy = oy + iy, gx = ox + ix;
        bool dom = ok && ((unsigned)gy < 127u) && ((unsigned)gx < 127u);
        if (ok) {
            xs0[p] = (dom && !zero) ? g_x[b * NN + gy * 127 + gx] : 0.0f;
            fs[p]  = dom ? f[b * NN + gy * 127 + gx] : 0.0f;
        }
        iyk[k] = iy; ixk[k] = ix; okk[k] = ok; domk[k] = dom;
    }
    __syncthreads();

    float* cur = xs0;
    float* nxt = xs1;
    for (int s = 0; s < 20; ++s) {
        int a = s + 1;
#pragma unroll
        for (int k = 0; k < 6; ++k) {
            if (okk[k]) {
                int p = tid + k * 1024;
                float nv = cur[p];
                int iy = iyk[k], ix = ixk[k];
                if (domk[k] && iy >= a && iy < JLT - a && ix >= a && ix < JLT - a) {
                    float ax = k0 * cur[p - JLT - 1] + k1 * cur[p - JLT] + k2 * cur[p - JLT + 1]
                             + k3 * cur[p - 1]       + k4 * cur[p]       + k5 * cur[p + 1]
                             + k6 * cur[p + JLT - 1] + k7 * cur[p + JLT] + k8 * cur[p + JLT + 1];
                    nv = cur[p] + tau * (fs[p] - ax);
                }
                nxt[p] = nv;
            }
        }
        __syncthreads();
        float* tsw = cur; cur = nxt; nxt = tsw;
    }

    // epilogue: 32x32 interior (1024 threads = exactly one px each)
    {
        int py = tid >> 5, px = tid & 31;
        int iy = JHL + py, ix = JHL + px;
        int gy = oy + iy, gx = ox + ix;
        if (((unsigned)gy < 127u) && ((unsigned)gx < 127u)) {
            int i = iy * JLT + ix;
            g_x[b * NN + gy * 127 + gx] = cur[i];
            float ax = k0 * cur[i - JLT - 1] + k1 * cur[i - JLT] + k2 * cur[i - JLT + 1]
                     + k3 * cur[i - 1]       + k4 * cur[i]       + k5 * cur[i + 1]
                     + k6 * cur[i + JLT - 1] + k7 * cur[i + JLT] + k8 * cur[i + JLT + 1];
            g_r[b * NN + gy * 127 + gx] = fs[i] - ax;
        }
    }
}

// ifft2 pass 1 (odd symmetry): FFT rows 1..127; store only k=0..127.
// 4 rows/block (256 threads).
__global__ void __launch_bounds__(256)
fft_row_expand(const int* __restrict__ ep, int iter) {
    if (iter >= get_K(ep)) return;
    __shared__ float2 s[4][256];
    __shared__ float2 tw[192];
    int b = blockIdx.y, t = threadIdx.x, ty = threadIdx.y;
    int y = blockIdx.x * 4 + ty + 1;            // 1..128 (128 invalid)
    bool ok = (y <= 127);
    build_tw(tw, ty * 64 + t, 1.0f);
    const float* rrow = g_r + (b * NN + (ok ? (y - 1) : 0) * 127);
#pragma unroll
    for (int k = 0; k < 4; ++k) {
        int p = t + k * 64;
        float v = 0.0f;
        if (ok) {
            if (p >= 1 && p <= 127)  v =  rrow[p - 1];
            else if (p >= 129)       v = -rrow[255 - p];
        }
        s[ty][dr4(p)] = make_float2(v, 0.0f);
    }
    __syncthreads();
#pragma unroll
    for (int st = 0; st < 4; ++st) {
        r4_bfly<1, 1>(s[ty], tw, t, st);
        __syncthreads();
    }
    if (ok) {
        float2* base = g_FA + (size_t)b * IMG;
#pragma unroll
        for (int k = 0; k < 2; ++k) {
            int kk = t + k * 64;
            float2 v0 = s[ty][kk];
            base[y * 256 + kk]         = v0;
            base[(256 - y) * 256 + kk] = make_float2(-v0.x, -v0.y);
            if (y == 1) {
                base[kk]             = make_float2(0.f, 0.f);
                base[128 * 256 + kk] = make_float2(0.f, 0.f);
            }
        }
    }
}

// ifft2 pass 2: columns 0..127, 16 cols/block, block (16,32)=512 thr,
// 2 butterflies/thread/stage; output purely REAL into g_FB (float view).
__global__ void __launch_bounds__(512)
fft_col_inv(const int* __restrict__ ep, int iter) {
    if (iter >= get_K(ep)) return;
    __shared__ float2 s[256 * 16];
    __shared__ float2 tw[192];
    int b  = blockIdx.y;
    int tx = threadIdx.x, ty = threadIdx.y;     // 16 x 32
    int tid = ty * 16 + tx;
    int x = blockIdx.x * 16 + tx;               // 0..127
    build_tw(tw, tid, 1.0f);
#pragma unroll
    for (int k = 0; k < 8; ++k) {
        int r = ty + k * 32;
        s[dr4(r) * 16 + tx] = g_FA[(b * 256 + r) * 256 + x];
    }
    __syncthreads();
#pragma unroll
    for (int st = 0; st < 4; ++st) {
        r4_bfly<16, 1>(s + tx, tw, ty, st);
        r4_bfly<16, 1>(s + tx, tw, ty + 32, st);
        __syncthreads();
    }
    const float sc = 1.0f / 65536.0f;
    float* FB = (float*)g_FB;
#pragma unroll
    for (int k = 0; k < 8; ++k) {
        int r = ty + k * 32;
        float val = s[r * 16 + tx].x * sc;
        int n2 = (r ^ 128);
        float* row = FB + (size_t)b * IMG + n2 * 256;
        if (x == 0) {
            row[128] = val;
            row[0]   = 0.0f;
        } else {
            row[x + 128] = val;
            row[128 - x] = -val;
        }
    }
}

// Composed 7x7 correlation, scalar FFMA, 256 threads x 4 px, independent chains.
template <bool ADJ>
__global__ void __launch_bounds__(256)
conv7(const float* __restrict__ inR, const float2* __restrict__ inC,
      float2* __restrict__ out,
      const float* __restrict__ thr, const float* __restrict__ thi,
      const int* __restrict__ ep, int iter) {
    if (iter >= get_K(ep)) return;
    __shared__ char smb[ADJ ? 38 * 38 * 8 : 38 * 38 * 4];
    __shared__ float Kr[49], Ki[49];
    float*  sr = (float*)smb;
    float2* sc = (float2*)smb;
    int b  = blockIdx.z;
    int ox = blockIdx.x * 32;
    int oy = blockIdx.y * 32;
    int tid = threadIdx.x;

    if (tid < 49) {
        float2 w = g_Kc[b * 98 + (ADJ ? 49 : 0) + tid];
        Kr[tid] = w.x;
        Ki[tid] = w.y;
    }
    for (int i = tid; i < 38 * 38; i += 256) {
        int iy = i / 38, ix = i - iy * 38;
        int gy = oy - 3 + iy, gx = ox - 3 + ix;
        bool in = ((unsigned)gy < 256u) && ((unsigned)gx < 256u);
        if (!ADJ) sr[i] = in ? inR[(size_t)b * IMG + gy * 256 + gx] : 0.0f;
        else      sc[i] = in ? inC[(size_t)b * IMG + gy * 256 + gx] : make_float2(0.f, 0.f);
    }
    __syncthreads();

    float aR[4] = {0.f, 0.f, 0.f, 0.f};
    float aI[4] = {0.f, 0.f, 0.f, 0.f};
    int base[4];
#pragma unroll
    for (int k = 0; k < 4; ++k) {
        int p = tid + k * 256;
        base[k] = (p >> 5) * 38 + (p & 31);
    }

    for (int dy = 0; dy < 7; ++dy) {
        int rowo = dy * 38;
#pragma unroll
        for (int dx = 0; dx < 7; ++dx) {
            float wr = Kr[dy * 7 + dx];
            float wi = Ki[dy * 7 + dx];
            int off = rowo + dx;
#pragma unroll
            for (int k = 0; k < 4; ++k) {
                if (!ADJ) {
                    float v = sr[base[k] + off];
                    aR[k] = fmaf(v, wr, aR[k]);
                    aI[k] = fmaf(v, wi, aI[k]);
                } else {
                    float2 v = sc[base[k] + off];
                    aR[k] = fmaf(v.x, wr, fmaf(-v.y, wi, aR[k]));
                    aI[k] = fmaf(v.x, wi, fmaf(v.y, wr, aI[k]));
                }
            }
        }
    }

#pragma unroll
    for (int k = 0; k < 4; ++k) {
        int p = tid + k * 256;
        int gidx = (oy + (p >> 5)) * 256 + (ox + (p & 31));
        float rr = aR[k], ii = aI[k];
        if (!ADJ) {
            float tr = thr[b * IMG + gidx], ti = thi[b * IMG + gidx];
            float nr = rr * tr - ii * ti;
            float ni = rr * ti + ii * tr;
            rr = nr; ii = ni;
        }
        out[(size_t)b * IMG + gidx] = make_float2(rr, ii);
    }
}

// fft2 pass 1: ifftshift on read, forward FFT along x; store k=0..127 only.
// 4 rows/block (256 threads).
__global__ void __launch_bounds__(256)
fft_row_fwd(const int* __restrict__ ep, int iter) {
    if (iter >= get_K(ep)) return;
    __shared__ float2 s[4][256];
    __shared__ float2 tw[192];
    int b = blockIdx.y, t = threadIdx.x, ty = threadIdx.y;
    int y = blockIdx.x * 4 + ty;
    build_tw(tw, ty * 64 + t, -1.0f);
    const float2* irow = g_FB + (b * 256 + (y ^ 128)) * 256;
#pragma unroll
    for (int k = 0; k < 4; ++k) {
        int p = t + k * 64;
        s[ty][dr4(p)] = irow[p ^ 128];
    }
    __syncthreads();
#pragma unroll
    for (int st = 0; st < 4; ++st) {
        r4_bfly<1, -1>(s[ty], tw, t, st);
        __syncthreads();
    }
    float2* orow = g_FA + (b * 256 + y) * 256;
    orow[t]      = s[ty][t];
    orow[t + 64] = s[ty][t + 64];
}

// fft2 pass 2: columns 0..127, block (16,32), crop 127x127, accumulate into x.
__global__ void __launch_bounds__(512)
fft_col_fwd_accum(const int* __restrict__ ep, int iter) {
    if (iter >= get_K(ep)) return;
    __shared__ float2 s[256 * 16];
    __shared__ float2 tw[192];
    int b  = blockIdx.y;
    int tx = threadIdx.x, ty = threadIdx.y;     // 16 x 32
    int tid = ty * 16 + tx;
    int x = blockIdx.x * 16 + tx;
    build_tw(tw, tid, -1.0f);
#pragma unroll
    for (int k = 0; k < 8; ++k) {
        int r = ty + k * 32;
        s[dr4(r) * 16 + tx] = g_FA[(b * 256 + r) * 256 + x];
    }
    __syncthreads();
#pragma unroll
    for (int st = 0; st < 4; ++st) {
        r4_bfly<16, -1>(s + tx, tw, ty, st);
        r4_bfly<16, -1>(s + tx, tw, ty + 32, st);
        __syncthreads();
    }
    if (x < 127) {
#pragma unroll
        for (int k = 0; k < 8; ++k) {
            int r = ty + k * 32;
            if (r < 127)
                g_x[b * NN + r * 127 + x] += s[r * 16 + tx].x;
        }
    }
}

// Residual norm.
__global__ void __launch_bounds__(256)
norm_partial(const float* __restrict__ f, const float* __restrict__ kA) {
    __shared__ float sr_s[256], sf_s[256];
    int b = blockIdx.y;
    int row = blockIdx.x * 2 + (threadIdx.x >> 7);
    int col = threadIdx.x & 127;
    float sr = 0.0f, sf = 0.0f;
    if (row < 127 && col < 127) {
        int p = row * 127 + col;
        const float* ka = kA + b * 9;
        const float* xb = g_x + b * NN;
        float s = 0.0f;
        if (row > 0) {
            if (col > 0)   s += ka[0] * xb[p - 128];
            s += ka[1] * xb[p - 127];
            if (col < 126) s += ka[2] * xb[p - 126];
        }
        if (col > 0)   s += ka[3] * xb[p - 1];
        s += ka[4] * xb[p];
        if (col < 126) s += ka[5] * xb[p + 1];
        if (row < 126) {
            if (col > 0)   s += ka[6] * xb[p + 126];
            s += ka[7] * xb[p + 127];
            if (col < 126) s += ka[8] * xb[p + 128];
        }
        float fv = f[b * NN + p];
        float rv = fv - s;
        sr = rv * rv;
        sf = fv * fv;
    }
    sr_s[threadIdx.x] = sr;
    sf_s[threadIdx.x] = sf;
    __syncthreads();
    for (int o = 128; o > 0; o >>= 1) {
        if (threadIdx.x < o) {
            sr_s[threadIdx.x] += sr_s[threadIdx.x + o];
            sf_s[threadIdx.x] += sf_s[threadIdx.x + o];
        }
        __syncthreads();
    }
    if (threadIdx.x == 0) g_part[b * 64 + blockIdx.x] = make_float2(sr_s[0], sf_s[0]);
}

__global__ void norm_final(float* __restrict__ out) {
    __shared__ float sr_s[256], sf_s[256];
    float sr = 0.0f, sf = 0.0f;
#pragma unroll
    for (int k = 0; k < 4; ++k) {
        float2 v = g_part[threadIdx.x + k * 256];
        sr += v.x; sf += v.y;
    }
    sr_s[threadIdx.x] = sr;
    sf_s[threadIdx.x] = sf;
    __syncthreads();
    for (int o = 128; o > 0; o >>= 1) {
        if (threadIdx.x < o) {
            sr_s[threadIdx.x] += sr_s[threadIdx.x + o];
            sf_s[threadIdx.x] += sf_s[threadIdx.x + o];
        }
        __syncthreads();
    }
    if (threadIdx.x == 0) out[0] = sqrtf(sr_s[0] / sf_s[0]);
}

// ---------------- launch ------------------------------------------------------
extern "C" void kernel_launch(void* const* d_in, const int* in_sizes, int n_in,
                              void* d_out, int out_size) {
    (void)in_sizes; (void)n_in; (void)out_size;
    const float* f   = (const float*)d_in[0];
    const float* kA  = (const float*)d_in[1];
    const float* w1r = (const float*)d_in[2];
    const float* w1i = (const float*)d_in[3];
    const float* w2r = (const float*)d_in[4];
    const float* w2i = (const float*)d_in[5];
    const float* w3r = (const float*)d_in[6];
    const float* w3i = (const float*)d_in[7];
    const float* thr = (const float*)d_in[8];
    const float* thi = (const float*)d_in[9];
    const int*   ep  = (const int*)d_in[10];
    float* out = (float*)d_out;

    void *pFA = nullptr, *pFB = nullptr;
    cudaGetSymbolAddress(&pFA, g_FA);
    cudaGetSymbolAddress(&pFB, g_FB);

    const int JSM = 3 * JLN * 4;   // 69312 B dynamic
    cudaFuncSetAttribute(jacobi_tile, cudaFuncAttributeMaxDynamicSharedMemorySize, JSM);

    compose_kernels<<<NB, 64>>>(w1r, w1i, w2r, w2i, w3r, w3i);

    dim3 jg(4, 4, NB);
    for (int it = 0; it < 3; ++it) {
        jacobi_tile<<<jg, 1024, JSM>>>(f, kA, ep, it, it == 0 ? 1 : 0);
        fft_row_expand<<<dim3(32, NB), dim3(64, 4)>>>(ep, it);
        fft_col_inv<<<dim3(8, NB), dim3(16, 32)>>>(ep, it);
        conv7<false><<<dim3(8, 8, NB), 256>>>(
            (const float*)pFB, nullptr, (float2*)pFA, thr, thi, ep, it);
        conv7<true><<<dim3(8, 8, NB), 256>>>(
            nullptr, (const float2*)pFA, (float2*)pFB, nullptr, nullptr, ep, it);
        fft_row_fwd<<<dim3(64, NB), dim3(64, 4)>>>(ep, it);
        fft_col_fwd_accum<<<dim3(8, NB), dim3(16, 32)>>>(ep, it);
    }

    norm_partial<<<dim3(64, NB), 256>>>(f, kA);
    norm_final<<<1, 256>>>(out);
}

// round 14
// speedup vs baseline: 1.1395x; 1.1395x over previous
#include <cuda_runtime.h>
#include <math.h>

#define NB   16
#define NI   127
#define NN   16129      // 127*127
#define IMG  65536      // 256*256
#define TS   32
#define HL2  11
#define LT2  54         // TS + 2*HL2
#define LTN  2916       // LT2*LT2

typedef unsigned long long u64;

// ---------------- scratch (static device globals) ----------------------------
static __device__ float  g_x[NB * NN];
static __device__ float  g_r[NB * NN];
static __device__ float2 g_FA[NB * IMG];
static __device__ float2 g_FB[NB * IMG];   // also reused as float (real) buffer
static __device__ float2 g_Kc[NB * 98];    // composed 7x7 kernels: [49 fwd | 49 adj]
static __device__ float2 g_part[1024];

// ---------------- misc helpers ------------------------------------------------
__device__ __forceinline__ int get_K(const int* ep) {
    int ei = *ep;
    int e;
    if (ei > 0 && ei <= 1000000) {
        e = ei;
    } else {
        float ff = __int_as_float(ei);
        e = (ff >= 1.0f && ff <= 1000000.0f) ? (int)ff : 120;
    }
    int K = (e - 1) / 40 + 1;
    if (K > 10) K = 10;
    if (K < 1)  K = 1;
    return K;
}

// base-4 digit reversal of 8-bit index
__device__ __forceinline__ int dr4(int p) {
    return ((p & 3) << 6) | (((p >> 2) & 3) << 4) | (((p >> 4) & 3) << 2) | ((p >> 6) & 3);
}

__device__ __forceinline__ float2 cmulf(float2 a, float2 b) {
    return make_float2(a.x * b.x - a.y * b.y, a.x * b.y + a.y * b.x);
}

__device__ __forceinline__ void build_tw(float2* tw, int tid, float sign) {
    if (tid < 192) {
        float s, c;
        __sincosf(sign * 6.283185307179586f * (float)tid * (1.0f / 256.0f), &s, &c);
        tw[tid] = make_float2(c, s);
    }
}

// Radix-4 256-pt DIT FFT, input base-4 digit-reversed, output natural.
template <int STRIDE, int SGN>
__device__ __forceinline__ void fft256_r4(float2* s, const float2* tw, int t) {
#pragma unroll
    for (int st = 0; st < 4; ++st) {
        int L    = 1 << (2 * st);
        int k    = t & (L - 1);
        int g    = t >> (2 * st);
        int i0   = g * 4 * L + k;
        int step = 64 >> (2 * st);
        float2 a = s[i0 * STRIDE];
        float2 b = s[(i0 + L) * STRIDE];
        float2 c = s[(i0 + 2 * L) * STRIDE];
        float2 d = s[(i0 + 3 * L) * STRIDE];
        b = cmulf(b, tw[k * step]);
        c = cmulf(c, tw[2 * k * step]);
        d = cmulf(d, tw[3 * k * step]);
        float2 t0 = make_float2(a.x + c.x, a.y + c.y);
        float2 t1 = make_float2(a.x - c.x, a.y - c.y);
        float2 t2 = make_float2(b.x + d.x, b.y + d.y);
        float2 t3 = make_float2(b.x - d.x, b.y - d.y);
        float2 rot = make_float2(-(float)SGN * t3.y, (float)SGN * t3.x);
        s[i0 * STRIDE]           = make_float2(t0.x + t2.x, t0.y + t2.y);
        s[(i0 + L) * STRIDE]     = make_float2(t1.x + rot.x, t1.y + rot.y);
        s[(i0 + 2 * L) * STRIDE] = make_float2(t0.x - t2.x, t0.y - t2.y);
        s[(i0 + 3 * L) * STRIDE] = make_float2(t1.x - rot.x, t1.y - rot.y);
        __syncthreads();
    }
}

// ---------------- kernels ----------------------------------------------------
// One-time: compose the 3-conv stacks into per-sample 7x7 correlation kernels.
__global__ void __launch_bounds__(64)
compose_kernels(const float* __restrict__ w1r, const float* __restrict__ w1i,
                const float* __restrict__ w2r, const float* __restrict__ w2i,
                const float* __restrict__ w3r, const float* __restrict__ w3i) {
    __shared__ float s1r[36], s1i[36], s2r[144], s2i[144], s3r[36], s3i[36];
    int b = blockIdx.x;
    int t = threadIdx.x;
    if (t < 36) { s1r[t] = w1r[b * 36 + t]; s1i[t] = w1i[b * 36 + t]; }
    if (t < 36) { s3r[t] = w3r[b * 36 + t]; s3i[t] = w3i[b * 36 + t]; }
    for (int i = t; i < 144; i += 64) { s2r[i] = w2r[b * 144 + i]; s2i[i] = w2i[b * 144 + i]; }
    __syncthreads();
    if (t >= 49) return;
    int my = t / 7 - 3, mx = t % 7 - 3;
    float fr = 0.f, fi = 0.f, ar = 0.f, ai = 0.f;
    for (int c2 = 0; c2 < 4; ++c2)
    for (int c1 = 0; c1 < 4; ++c1)
    for (int j = 0; j < 9; ++j) {
        int jy = j / 3 - 1, jx = j % 3 - 1;
        for (int k = 0; k < 9; ++k) {
            int ky = k / 3 - 1, kx = k % 3 - 1;
            int ly = my - jy - ky, lx = mx - jx - kx;
            if (ly < -1 || ly > 1 || lx < -1 || lx > 1) continue;
            int l = (ly + 1) * 3 + (lx + 1);
            {
                float xr = s3r[c2 * 9 + j],            xi = s3i[c2 * 9 + j];
                float yr = s2r[(c2 * 4 + c1) * 9 + k], yi = s2i[(c2 * 4 + c1) * 9 + k];
                float zr = s1r[c1 * 9 + l],            zi = s1i[c1 * 9 + l];
                float pr = xr * yr - xi * yi, pi = xr * yi + xi * yr;
                fr += pr * zr - pi * zi;
                fi += pr * zi + pi * zr;
            }
            {
                int jT = (j % 3) * 3 + j / 3;
                int kT = (k % 3) * 3 + k / 3;
                int lT = (l % 3) * 3 + l / 3;
                float xr = s1r[c2 * 9 + jT],            xi = -s1i[c2 * 9 + jT];
                float yr = s2r[(c1 * 4 + c2) * 9 + kT], yi = -s2i[(c1 * 4 + c2) * 9 + kT];
                float zr = s3r[c1 * 9 + lT],            zi = -s3i[c1 * 9 + lT];
                float pr = xr * yr - xi * yi, pi = xr * yi + xi * yr;
                ar += pr * zr - pi * zi;
                ai += pr * zi + pi * zr;
            }
        }
    }
    g_Kc[b * 98 + t]      = make_float2(fr, fi);
    g_Kc[b * 98 + 49 + t] = make_float2(ar, ai);
}

// Sweep-chunked Jacobi: 10 sweeps/launch on 54x54 tiles (halo 11), 512 threads.
__global__ void __launch_bounds__(512)
jacobi_tile(const float* __restrict__ f, const float* __restrict__ kA,
            const int* __restrict__ ep, int iter, int final_, int zero) {
    if (iter >= get_K(ep)) return;
    __shared__ float xs0[LTN], xs1[LTN], fs[LTN];
    int b  = blockIdx.z;
    int ox = blockIdx.x * TS - HL2;
    int oy = blockIdx.y * TS - HL2;
    int tid = threadIdx.x;
    const float* ka = kA + b * 9;
    float k0 = ka[0], k1 = ka[1], k2 = ka[2], k3 = ka[3], k4 = ka[4];
    float k5 = ka[5], k6 = ka[6], k7 = ka[7], k8 = ka[8];
    float tau = 0.5f / k4;

    int  iyk[6], ixk[6];
    bool okk[6], domk[6];
#pragma unroll
    for (int k = 0; k < 6; ++k) {
        int p = tid + k * 512;
        bool ok = p < LTN;
        int iy = 0, ix = 0;
        if (ok) { iy = p / LT2; ix = p - iy * LT2; }
        int gy = oy + iy, gx = ox + ix;
        bool dom = ok && ((unsigned)gy < 127u) && ((unsigned)gx < 127u);
        if (ok) {
            xs0[p] = (dom && !zero) ? g_x[b * NN + gy * 127 + gx] : 0.0f;
            fs[p]  = dom ? f[b * NN + gy * 127 + gx] : 0.0f;
        }
        iyk[k] = iy; ixk[k] = ix; okk[k] = ok; domk[k] = dom;
    }
    __syncthreads();

    float* cur = xs0;
    float* nxt = xs1;
#pragma unroll
    for (int s = 0; s < 10; ++s) {
        int a = s + 1;
#pragma unroll
        for (int k = 0; k < 6; ++k) {
            if (okk[k]) {
                int p = tid + k * 512;
                float nv = cur[p];
                int iy = iyk[k], ix = ixk[k];
                if (domk[k] && iy >= a && iy < LT2 - a && ix >= a && ix < LT2 - a) {
                    float ax = k0 * cur[p - LT2 - 1] + k1 * cur[p - LT2] + k2 * cur[p - LT2 + 1]
                             + k3 * cur[p - 1]       + k4 * cur[p]       + k5 * cur[p + 1]
                             + k6 * cur[p + LT2 - 1] + k7 * cur[p + LT2] + k8 * cur[p + LT2 + 1];
                    nv = cur[p] + tau * (fs[p] - ax);
                }
                nxt[p] = nv;
            }
        }
        __syncthreads();
        float* tsw = cur; cur = nxt; nxt = tsw;
    }

#pragma unroll
    for (int k = 0; k < 2; ++k) {
        int p2 = tid + k * 512;
        int py = p2 >> 5, px = p2 & 31;
        int iy = HL2 + py, ix = HL2 + px;
        int gy = oy + iy, gx = ox + ix;
        if (((unsigned)gy < 127u) && ((unsigned)gx < 127u)) {
            int i = iy * LT2 + ix;
            g_x[b * NN + gy * 127 + gx] = cur[i];
            if (final_) {
                float ax = k0 * cur[i - LT2 - 1] + k1 * cur[i - LT2] + k2 * cur[i - LT2 + 1]
                         + k3 * cur[i - 1]       + k4 * cur[i]       + k5 * cur[i + 1]
                         + k6 * cur[i + LT2 - 1] + k7 * cur[i + LT2] + k8 * cur[i + LT2 + 1];
                g_r[b * NN + gy * 127 + gx] = fs[i] - ax;
            }
        }
    }
}

// ifft2 pass 1 (odd symmetry): FFT rows 1..127; store only k=0..127.
__global__ void __launch_bounds__(512)
fft_row_expand(const int* __restrict__ ep, int iter) {
    if (iter >= get_K(ep)) return;
    __shared__ float2 s[8][256];
    __shared__ float2 tw[192];
    int b = blockIdx.y, t = threadIdx.x, ty = threadIdx.y;
    int y = blockIdx.x * 8 + ty + 1;
    bool ok = (y <= 127);
    build_tw(tw, ty * 64 + t, 1.0f);
    const float* rrow = g_r + (b * NN + (ok ? (y - 1) : 0) * 127);
#pragma unroll
    for (int k = 0; k < 4; ++k) {
        int p = t + k * 64;
        float v = 0.0f;
        if (ok) {
            if (p >= 1 && p <= 127)  v =  rrow[p - 1];
            else if (p >= 129)       v = -rrow[255 - p];
        }
        s[ty][dr4(p)] = make_float2(v, 0.0f);
    }
    __syncthreads();
    fft256_r4<1, 1>(s[ty], tw, t);
    if (ok) {
        float2* base = g_FA + (size_t)b * IMG;
#pragma unroll
        for (int k = 0; k < 2; ++k) {
            int kk = t + k * 64;
            float2 v0 = s[ty][kk];
            base[y * 256 + kk]         = v0;
            base[(256 - y) * 256 + kk] = make_float2(-v0.x, -v0.y);
            if (y == 1) {
                base[kk]             = make_float2(0.f, 0.f);
                base[128 * 256 + kk] = make_float2(0.f, 0.f);
            }
        }
    }
}

// ifft2 pass 2: columns 0..127; output purely REAL into g_FB (float view).
__global__ void __launch_bounds__(1024)
fft_col_inv(const int* __restrict__ ep, int iter) {
    if (iter >= get_K(ep)) return;
    __shared__ float2 s[256 * 16];
    __shared__ float2 tw[192];
    int b  = blockIdx.y;
    int tx = threadIdx.x, ty = threadIdx.y;     // 16 x 64
    int tid = ty * 16 + tx;
    int x = blockIdx.x * 16 + tx;               // 0..127
    build_tw(tw, tid, 1.0f);
#pragma unroll
    for (int k = 0; k < 4; ++k) {
        int r = ty + k * 64;
        s[dr4(r) * 16 + tx] = g_FA[(b * 256 + r) * 256 + x];
    }
    __syncthreads();
    fft256_r4<16, 1>(s + tx, tw, ty);
    const float sc = 1.0f / 65536.0f;
    float* FB = (float*)g_FB;
#pragma unroll
    for (int k = 0; k < 4; ++k) {
        int r = ty + k * 64;
        float val = s[r * 16 + tx].x * sc;
        int n2 = (r ^ 128);
        float* row = FB + (size_t)b * IMG + n2 * 256;
        if (x == 0) {
            row[128] = val;
            row[0]   = 0.0f;
        } else {
            row[x + 128] = val;
            row[128 - x] = -val;
        }
    }
}

// Composed 7x7 correlation with horizontal 4-px register tiling.
// 256 threads: py = tid>>3 (0..31), px0 = (tid&7)*4. Sliding 10-wide window
// per tap-row -> 10 smem loads serve 4 outputs x 7 taps.
// ADJ=false: real input (g_FB float view), *theta, write g_FA.
// ADJ=true : complex input g_FA, write g_FB.
template <bool ADJ>
__global__ void __launch_bounds__(256)
conv7(const float* __restrict__ inR, const float2* __restrict__ inC,
      float2* __restrict__ out,
      const float* __restrict__ thr, const float* __restrict__ thi,
      const int* __restrict__ ep, int iter) {
    if (iter >= get_K(ep)) return;
    __shared__ char smb[ADJ ? 38 * 38 * 8 : 38 * 38 * 4];
    __shared__ float Kr[49], Ki[49];
    float*  sr = (float*)smb;
    float2* sc = (float2*)smb;
    int b  = blockIdx.z;
    int ox = blockIdx.x * 32;
    int oy = blockIdx.y * 32;
    int tid = threadIdx.x;

    if (tid < 49) {
        float2 w = g_Kc[b * 98 + (ADJ ? 49 : 0) + tid];
        Kr[tid] = w.x;
        Ki[tid] = w.y;
    }
    for (int i = tid; i < 38 * 38; i += 256) {
        int iy = i / 38, ix = i - iy * 38;
        int gy = oy - 3 + iy, gx = ox - 3 + ix;
        bool in = ((unsigned)gy < 256u) && ((unsigned)gx < 256u);
        if (!ADJ) sr[i] = in ? inR[(size_t)b * IMG + gy * 256 + gx] : 0.0f;
        else      sc[i] = in ? inC[(size_t)b * IMG + gy * 256 + gx] : make_float2(0.f, 0.f);
    }
    __syncthreads();

    int py  = tid >> 3;
    int px0 = (tid & 7) * 4;
    int base = py * 38 + px0;

    float aR[4] = {0.f, 0.f, 0.f, 0.f};
    float aI[4] = {0.f, 0.f, 0.f, 0.f};

    for (int dy = 0; dy < 7; ++dy) {
        int rowo = base + dy * 38;
        if (!ADJ) {
            float v[10];
#pragma unroll
            for (int j = 0; j < 10; ++j) v[j] = sr[rowo + j];
#pragma unroll
            for (int dx = 0; dx < 7; ++dx) {
                float wr = Kr[dy * 7 + dx];
                float wi = Ki[dy * 7 + dx];
#pragma unroll
                for (int k = 0; k < 4; ++k) {
                    aR[k] = fmaf(v[dx + k], wr, aR[k]);
                    aI[k] = fmaf(v[dx + k], wi, aI[k]);
                }
            }
        } else {
            float2 v[10];
#pragma unroll
            for (int j = 0; j < 10; ++j) v[j] = sc[rowo + j];
#pragma unroll
            for (int dx = 0; dx < 7; ++dx) {
                float wr = Kr[dy * 7 + dx];
                float wi = Ki[dy * 7 + dx];
#pragma unroll
                for (int k = 0; k < 4; ++k) {
                    aR[k] = fmaf(v[dx + k].x, wr, fmaf(-v[dx + k].y, wi, aR[k]));
                    aI[k] = fmaf(v[dx + k].x, wi, fmaf(v[dx + k].y, wr, aI[k]));
                }
            }
        }
    }

    int grow = (oy + py) * 256 + ox + px0;
#pragma unroll
    for (int k = 0; k < 4; ++k) {
        int gidx = grow + k;
        float rr = aR[k], ii = aI[k];
        if (!ADJ) {
            float tr = thr[b * IMG + gidx], ti = thi[b * IMG + gidx];
            float nr = rr * tr - ii * ti;
            float ni = rr * ti + ii * tr;
            rr = nr; ii = ni;
        }
        out[(size_t)b * IMG + gidx] = make_float2(rr, ii);
    }
}

// fft2 pass 1: ifftshift on read, forward FFT along x; store k=0..127 only.
__global__ void __launch_bounds__(512)
fft_row_fwd(const int* __restrict__ ep, int iter) {
    if (iter >= get_K(ep)) return;
    __shared__ float2 s[8][256];
    __shared__ float2 tw[192];
    int b = blockIdx.y, t = threadIdx.x, ty = threadIdx.y;
    int y = blockIdx.x * 8 + ty;
    build_tw(tw, ty * 64 + t, -1.0f);
    const float2* irow = g_FB + (b * 256 + (y ^ 128)) * 256;
#pragma unroll
    for (int k = 0; k < 4; ++k) {
        int p = t + k * 64;
        s[ty][dr4(p)] = irow[p ^ 128];
    }
    __syncthreads();
    fft256_r4<1, -1>(s[ty], tw, t);
    float2* orow = g_FA + (b * 256 + y) * 256;
    orow[t]      = s[ty][t];
    orow[t + 64] = s[ty][t + 64];
}

// fft2 pass 2: columns 0..127, crop 127x127, accumulate into x.
__global__ void __launch_bounds__(1024)
fft_col_fwd_accum(const int* __restrict__ ep, int iter) {
    if (iter >= get_K(ep)) return;
    __shared__ float2 s[256 * 16];
    __shared__ float2 tw[192];
    int b  = blockIdx.y;
    int tx = threadIdx.x, ty = threadIdx.y;     // 16 x 64
    int tid = ty * 16 + tx;
    int x = blockIdx.x * 16 + tx;
    build_tw(tw, tid, -1.0f);
#pragma unroll
    for (int k = 0; k < 4; ++k) {
        int r = ty + k * 64;
        s[dr4(r) * 16 + tx] = g_FA[(b * 256 + r) * 256 + x];
    }
    __syncthreads();
    fft256_r4<16, -1>(s + tx, tw, ty);
    if (x < 127) {
#pragma unroll
        for (int k = 0; k < 4; ++k) {
            int r = ty + k * 64;
            if (r < 127)
                g_x[b * NN + r * 127 + x] += s[r * 16 + tx].x;
        }
    }
}

// Residual norm.
__global__ void __launch_bounds__(256)
norm_partial(const float* __restrict__ f, const float* __restrict__ kA) {
    __shared__ float sr_s[256], sf_s[256];
    int b = blockIdx.y;
    int row = blockIdx.x * 2 + (threadIdx.x >> 7);
    int col = threadIdx.x & 127;
    float sr = 0.0f, sf = 0.0f;
    if (row < 127 && col < 127) {
        int p = row * 127 + col;
        const float* ka = kA + b * 9;
        const float* xb = g_x + b * NN;
        float s = 0.0f;
        if (row > 0) {
            if (col > 0)   s += ka[0] * xb[p - 128];
            s += ka[1] * xb[p - 127];
            if (col < 126) s += ka[2] * xb[p - 126];
        }
        if (col > 0)   s += ka[3] * xb[p - 1];
        s += ka[4] * xb[p];
        if (col < 126) s += ka[5] * xb[p + 1];
        if (row < 126) {
            if (col > 0)   s += ka[6] * xb[p + 126];
            s += ka[7] * xb[p + 127];
            if (col < 126) s += ka[8] * xb[p + 128];
        }
        float fv = f[b * NN + p];
        float rv = fv - s;
        sr = rv * rv;
        sf = fv * fv;
    }
    sr_s[threadIdx.x] = sr;
    sf_s[threadIdx.x] = sf;
    __syncthreads();
    for (int o = 128; o > 0; o >>= 1) {
        if (threadIdx.x < o) {
            sr_s[threadIdx.x] += sr_s[threadIdx.x + o];
            sf_s[threadIdx.x] += sf_s[threadIdx.x + o];
        }
        __syncthreads();
    }
    if (threadIdx.x == 0) g_part[b * 64 + blockIdx.x] = make_float2(sr_s[0], sf_s[0]);
}

__global__ void norm_final(float* __restrict__ out) {
    __shared__ float sr_s[256], sf_s[256];
    float sr = 0.0f, sf = 0.0f;
#pragma unroll
    for (int k = 0; k < 4; ++k) {
        float2 v = g_part[threadIdx.x + k * 256];
        sr += v.x; sf += v.y;
    }
    sr_s[threadIdx.x] = sr;
    sf_s[threadIdx.x] = sf;
    __syncthreads();
    for (int o = 128; o > 0; o >>= 1) {
        if (threadIdx.x < o) {
            sr_s[threadIdx.x] += sr_s[threadIdx.x + o];
            sf_s[threadIdx.x] += sf_s[threadIdx.x + o];
        }
        __syncthreads();
    }
    if (threadIdx.x == 0) out[0] = sqrtf(sr_s[0] / sf_s[0]);
}

// ---------------- launch ------------------------------------------------------
extern "C" void kernel_launch(void* const* d_in, const int* in_sizes, int n_in,
                              void* d_out, int out_size) {
    (void)in_sizes; (void)n_in; (void)out_size;
    const float* f   = (const float*)d_in[0];
    const float* kA  = (const float*)d_in[1];
    const float* w1r = (const float*)d_in[2];
    const float* w1i = (const float*)d_in[3];
    const float* w2r = (const float*)d_in[4];
    const float* w2i = (const float*)d_in[5];
    const float* w3r = (const float*)d_in[6];
    const float* w3i = (const float*)d_in[7];
    const float* thr = (const float*)d_in[8];
    const float* thi = (const float*)d_in[9];
    const int*   ep  = (const int*)d_in[10];
    float* out = (float*)d_out;

    void *pFA = nullptr, *pFB = nullptr;
    cudaGetSymbolAddress(&pFA, g_FA);
    cudaGetSymbolAddress(&pFB, g_FB);

    compose_kernels<<<NB, 64>>>(w1r, w1i, w2r, w2i, w3r, w3i);

    dim3 jg(4, 4, NB);
    for (int it = 0; it < 3; ++it) {
        jacobi_tile<<<jg, 512>>>(f, kA, ep, it, 0, it == 0 ? 1 : 0);
        jacobi_tile<<<jg, 512>>>(f, kA, ep, it, 1, 0);
        fft_row_expand<<<dim3(16, NB), dim3(64, 8)>>>(ep, it);
        fft_col_inv<<<dim3(8, NB), dim3(16, 64)>>>(ep, it);
        conv7<false><<<dim3(8, 8, NB), 256>>>(
            (const float*)pFB, nullptr, (float2*)pFA, thr, thi, ep, it);
        conv7<true><<<dim3(8, 8, NB), 256>>>(
            nullptr, (const float2*)pFA, (float2*)pFB, nullptr, nullptr, ep, it);
        fft_row_fwd<<<dim3(32, NB), dim3(64, 8)>>>(ep, it);
        fft_col_fwd_accum<<<dim3(8, NB), dim3(16, 64)>>>(ep, it);
    }

    norm_partial<<<dim3(64, NB), 256>>>(f, kA);
    norm_final<<<1, 256>>>(out);
}

// round 15
// speedup vs baseline: 1.1697x; 1.0265x over previous
#include <cuda_runtime.h>
#include <math.h>

#define NB   16
#define NI   127
#define NN   16129      // 127*127
#define IMG  65536      // 256*256
#define TS   32
#define HL2  11
#define LT2  54         // TS + 2*HL2
#define LTN  2916       // LT2*LT2

typedef unsigned long long u64;

// ---------------- scratch (static device globals) ----------------------------
static __device__ float  g_x[NB * NN];
static __device__ float  g_r[NB * NN];
static __device__ float2 g_FA[NB * IMG];
static __device__ float2 g_FB[NB * IMG];   // also reused as float (real) buffer
static __device__ float2 g_Kc[NB * 98];    // composed 7x7 kernels: [49 fwd | 49 adj]
static __device__ float2 g_part[1024];

// ---------------- misc helpers ------------------------------------------------
__device__ __forceinline__ int get_K(const int* ep) {
    int ei = *ep;
    int e;
    if (ei > 0 && ei <= 1000000) {
        e = ei;
    } else {
        float ff = __int_as_float(ei);
        e = (ff >= 1.0f && ff <= 1000000.0f) ? (int)ff : 120;
    }
    int K = (e - 1) / 40 + 1;
    if (K > 10) K = 10;
    if (K < 1)  K = 1;
    return K;
}

__device__ __forceinline__ int dr4(int p) {
    return ((p & 3) << 6) | (((p >> 2) & 3) << 4) | (((p >> 4) & 3) << 2) | ((p >> 6) & 3);
}

__device__ __forceinline__ float2 cmulf(float2 a, float2 b) {
    return make_float2(a.x * b.x - a.y * b.y, a.x * b.y + a.y * b.x);
}

__device__ __forceinline__ void build_tw(float2* tw, int tid, float sign) {
    if (tid < 192) {
        float s, c;
        __sincosf(sign * 6.283185307179586f * (float)tid * (1.0f / 256.0f), &s, &c);
        tw[tid] = make_float2(c, s);
    }
}

// Radix-4 256-pt DIT FFT, input base-4 digit-reversed, output natural.
template <int STRIDE, int SGN>
__device__ __forceinline__ void fft256_r4(float2* s, const float2* tw, int t) {
#pragma unroll
    for (int st = 0; st < 4; ++st) {
        int L    = 1 << (2 * st);
        int k    = t & (L - 1);
        int g    = t >> (2 * st);
        int i0   = g * 4 * L + k;
        int step = 64 >> (2 * st);
        float2 a = s[i0 * STRIDE];
        float2 b = s[(i0 + L) * STRIDE];
        float2 c = s[(i0 + 2 * L) * STRIDE];
        float2 d = s[(i0 + 3 * L) * STRIDE];
        b = cmulf(b, tw[k * step]);
        c = cmulf(c, tw[2 * k * step]);
        d = cmulf(d, tw[3 * k * step]);
        float2 t0 = make_float2(a.x + c.x, a.y + c.y);
        float2 t1 = make_float2(a.x - c.x, a.y - c.y);
        float2 t2 = make_float2(b.x + d.x, b.y + d.y);
        float2 t3 = make_float2(b.x - d.x, b.y - d.y);
        float2 rot = make_float2(-(float)SGN * t3.y, (float)SGN * t3.x);
        s[i0 * STRIDE]           = make_float2(t0.x + t2.x, t0.y + t2.y);
        s[(i0 + L) * STRIDE]     = make_float2(t1.x + rot.x, t1.y + rot.y);
        s[(i0 + 2 * L) * STRIDE] = make_float2(t0.x - t2.x, t0.y - t2.y);
        s[(i0 + 3 * L) * STRIDE] = make_float2(t1.x - rot.x, t1.y - rot.y);
        __syncthreads();
    }
}

// ---------------- kernels ----------------------------------------------------
// One-time: compose the 3-conv stacks into per-sample 7x7 correlation kernels.
__global__ void __launch_bounds__(64)
compose_kernels(const float* __restrict__ w1r, const float* __restrict__ w1i,
                const float* __restrict__ w2r, const float* __restrict__ w2i,
                const float* __restrict__ w3r, const float* __restrict__ w3i) {
    __shared__ float s1r[36], s1i[36], s2r[144], s2i[144], s3r[36], s3i[36];
    int b = blockIdx.x;
    int t = threadIdx.x;
    if (t < 36) { s1r[t] = w1r[b * 36 + t]; s1i[t] = w1i[b * 36 + t]; }
    if (t < 36) { s3r[t] = w3r[b * 36 + t]; s3i[t] = w3i[b * 36 + t]; }
    for (int i = t; i < 144; i += 64) { s2r[i] = w2r[b * 144 + i]; s2i[i] = w2i[b * 144 + i]; }
    __syncthreads();
    if (t >= 49) return;
    int my = t / 7 - 3, mx = t % 7 - 3;
    float fr = 0.f, fi = 0.f, ar = 0.f, ai = 0.f;
    for (int c2 = 0; c2 < 4; ++c2)
    for (int c1 = 0; c1 < 4; ++c1)
    for (int j = 0; j < 9; ++j) {
        int jy = j / 3 - 1, jx = j % 3 - 1;
        for (int k = 0; k < 9; ++k) {
            int ky = k / 3 - 1, kx = k % 3 - 1;
            int ly = my - jy - ky, lx = mx - jx - kx;
            if (ly < -1 || ly > 1 || lx < -1 || lx > 1) continue;
            int l = (ly + 1) * 3 + (lx + 1);
            {
                float xr = s3r[c2 * 9 + j],            xi = s3i[c2 * 9 + j];
                float yr = s2r[(c2 * 4 + c1) * 9 + k], yi = s2i[(c2 * 4 + c1) * 9 + k];
                float zr = s1r[c1 * 9 + l],            zi = s1i[c1 * 9 + l];
                float pr = xr * yr - xi * yi, pi = xr * yi + xi * yr;
                fr += pr * zr - pi * zi;
                fi += pr * zi + pi * zr;
            }
            {
                int jT = (j % 3) * 3 + j / 3;
                int kT = (k % 3) * 3 + k / 3;
                int lT = (l % 3) * 3 + l / 3;
                float xr = s1r[c2 * 9 + jT],            xi = -s1i[c2 * 9 + jT];
                float yr = s2r[(c1 * 4 + c2) * 9 + kT], yi = -s2i[(c1 * 4 + c2) * 9 + kT];
                float zr = s3r[c1 * 9 + lT],            zi = -s3i[c1 * 9 + lT];
                float pr = xr * yr - xi * yi, pi = xr * yi + xi * yr;
                ar += pr * zr - pi * zi;
                ai += pr * zi + pi * zr;
            }
        }
    }
    g_Kc[b * 98 + t]      = make_float2(fr, fi);
    g_Kc[b * 98 + 49 + t] = make_float2(ar, ai);
}

// Sweep-chunked Jacobi: 10 sweeps/launch on 54x54 tiles (halo 11), 512 threads.
__global__ void __launch_bounds__(512)
jacobi_tile(const float* __restrict__ f, const float* __restrict__ kA,
            const int* __restrict__ ep, int iter, int final_, int zero) {
    if (iter >= get_K(ep)) return;
    __shared__ float xs0[LTN], xs1[LTN], fs[LTN];
    int b  = blockIdx.z;
    int ox = blockIdx.x * TS - HL2;
    int oy = blockIdx.y * TS - HL2;
    int tid = threadIdx.x;
    const float* ka = kA + b * 9;
    float k0 = ka[0], k1 = ka[1], k2 = ka[2], k3 = ka[3], k4 = ka[4];
    float k5 = ka[5], k6 = ka[6], k7 = ka[7], k8 = ka[8];
    float tau = 0.5f / k4;

    int  iyk[6], ixk[6];
    bool okk[6], domk[6];
#pragma unroll
    for (int k = 0; k < 6; ++k) {
        int p = tid + k * 512;
        bool ok = p < LTN;
        int iy = 0, ix = 0;
        if (ok) { iy = p / LT2; ix = p - iy * LT2; }
        int gy = oy + iy, gx = ox + ix;
        bool dom = ok && ((unsigned)gy < 127u) && ((unsigned)gx < 127u);
        if (ok) {
            xs0[p] = (dom && !zero) ? g_x[b * NN + gy * 127 + gx] : 0.0f;
            fs[p]  = dom ? f[b * NN + gy * 127 + gx] : 0.0f;
        }
        iyk[k] = iy; ixk[k] = ix; okk[k] = ok; domk[k] = dom;
    }
    __syncthreads();

    float* cur = xs0;
    float* nxt = xs1;
#pragma unroll
    for (int s = 0; s < 10; ++s) {
        int a = s + 1;
#pragma unroll
        for (int k = 0; k < 6; ++k) {
            if (okk[k]) {
                int p = tid + k * 512;
                float nv = cur[p];
                int iy = iyk[k], ix = ixk[k];
                if (domk[k] && iy >= a && iy < LT2 - a && ix >= a && ix < LT2 - a) {
                    float ax = k0 * cur[p - LT2 - 1] + k1 * cur[p - LT2] + k2 * cur[p - LT2 + 1]
                             + k3 * cur[p - 1]       + k4 * cur[p]       + k5 * cur[p + 1]
                             + k6 * cur[p + LT2 - 1] + k7 * cur[p + LT2] + k8 * cur[p + LT2 + 1];
                    nv = cur[p] + tau * (fs[p] - ax);
                }
                nxt[p] = nv;
            }
        }
        __syncthreads();
        float* tsw = cur; cur = nxt; nxt = tsw;
    }

#pragma unroll
    for (int k = 0; k < 2; ++k) {
        int p2 = tid + k * 512;
        int py = p2 >> 5, px = p2 & 31;
        int iy = HL2 + py, ix = HL2 + px;
        int gy = oy + iy, gx = ox + ix;
        if (((unsigned)gy < 127u) && ((unsigned)gx < 127u)) {
            int i = iy * LT2 + ix;
            g_x[b * NN + gy * 127 + gx] = cur[i];
            if (final_) {
                float ax = k0 * cur[i - LT2 - 1] + k1 * cur[i - LT2] + k2 * cur[i - LT2 + 1]
                         + k3 * cur[i - 1]       + k4 * cur[i]       + k5 * cur[i + 1]
                         + k6 * cur[i + LT2 - 1] + k7 * cur[i + LT2] + k8 * cur[i + LT2 + 1];
                g_r[b * NN + gy * 127 + gx] = fs[i] - ax;
            }
        }
    }
}

// ifft2 pass 1, packed: two real expanded rows per complex FFT.
// z_j = row(2j+1) + i*row(2j+2), j=0..62; j=63 -> row 127 alone.
// Separate via conjugate symmetry; store k=0..127 of rows y and 256-y.
__global__ void __launch_bounds__(256)
fft_row_expand(const int* __restrict__ ep, int iter) {
    if (iter >= get_K(ep)) return;
    __shared__ float2 s[4][256];
    __shared__ float2 tw[192];
    int b = blockIdx.y, t = threadIdx.x, ty = threadIdx.y;
    int j = blockIdx.x * 4 + ty;                // 0..63
    int y1 = 2 * j + 1;                         // 1,3,..,127
    int y2 = 2 * j + 2;                         // 2,4,..,128 (128 unused)
    bool two = (j < 63);
    build_tw(tw, ty * 64 + t, 1.0f);
    const float* r1 = g_r + (b * NN + (y1 - 1) * 127);
    const float* r2 = g_r + (b * NN + (two ? (y2 - 1) : 0) * 127);
#pragma unroll
    for (int k = 0; k < 4; ++k) {
        int p = t + k * 64;
        float v1 = 0.0f, v2 = 0.0f;
        if (p >= 1 && p <= 127) {
            v1 = r1[p - 1];
            if (two) v2 = r2[p - 1];
        } else if (p >= 129) {
            v1 = -r1[255 - p];
            if (two) v2 = -r2[255 - p];
        }
        s[ty][dr4(p)] = make_float2(v1, v2);
    }
    __syncthreads();
    fft256_r4<1, 1>(s[ty], tw, t);
    float2* base = g_FA + (size_t)b * IMG;
#pragma unroll
    for (int k = 0; k < 2; ++k) {
        int kk = t + k * 64;                    // 0..127
        float2 Zk = s[ty][kk];
        float2 Zm = s[ty][(256 - kk) & 255];
        float sr_ = Zk.x + Zm.x, si_ = Zk.y - Zm.y;   // Z[k] + conj(Z[N-k])
        float dr_ = Zk.x - Zm.x, di_ = Zk.y + Zm.y;   // Z[k] - conj(Z[N-k])
        float2 F1 = make_float2(0.5f * sr_, 0.5f * si_);
        float2 F2 = make_float2(0.5f * di_, -0.5f * dr_);
        base[y1 * 256 + kk]         = F1;
        base[(256 - y1) * 256 + kk] = make_float2(-F1.x, -F1.y);
        if (two) {
            base[y2 * 256 + kk]         = F2;
            base[(256 - y2) * 256 + kk] = make_float2(-F2.x, -F2.y);
        }
    }
    if (blockIdx.x == 0 && ty == 0) {           // zero rows 0 and 128
#pragma unroll
        for (int k = 0; k < 2; ++k) {
            int kk = t + k * 64;
            base[kk]             = make_float2(0.f, 0.f);
            base[128 * 256 + kk] = make_float2(0.f, 0.f);
        }
    }
}

// ifft2 pass 2: columns 0..127; output purely REAL into g_FB (float view).
__global__ void __launch_bounds__(1024)
fft_col_inv(const int* __restrict__ ep, int iter) {
    if (iter >= get_K(ep)) return;
    __shared__ float2 s[256 * 16];
    __shared__ float2 tw[192];
    int b  = blockIdx.y;
    int tx = threadIdx.x, ty = threadIdx.y;     // 16 x 64
    int tid = ty * 16 + tx;
    int x = blockIdx.x * 16 + tx;               // 0..127
    build_tw(tw, tid, 1.0f);
#pragma unroll
    for (int k = 0; k < 4; ++k) {
        int r = ty + k * 64;
        s[dr4(r) * 16 + tx] = g_FA[(b * 256 + r) * 256 + x];
    }
    __syncthreads();
    fft256_r4<16, 1>(s + tx, tw, ty);
    const float sc = 1.0f / 65536.0f;
    float* FB = (float*)g_FB;
#pragma unroll
    for (int k = 0; k < 4; ++k) {
        int r = ty + k * 64;
        float val = s[r * 16 + tx].x * sc;
        int n2 = (r ^ 128);
        float* row = FB + (size_t)b * IMG + n2 * 256;
        if (x == 0) {
            row[128] = val;
            row[0]   = 0.0f;
        } else {
            row[x + 128] = val;
            row[128 - x] = -val;
        }
    }
}

// Composed 7x7 correlation with horizontal 4-px register tiling.
template <bool ADJ>
__global__ void __launch_bounds__(256)
conv7(const float* __restrict__ inR, const float2* __restrict__ inC,
      float2* __restrict__ out,
      const float* __restrict__ thr, const float* __restrict__ thi,
      const int* __restrict__ ep, int iter) {
    if (iter >= get_K(ep)) return;
    __shared__ char smb[ADJ ? 38 * 38 * 8 : 38 * 38 * 4];
    __shared__ float Kr[49], Ki[49];
    float*  sr = (float*)smb;
    float2* sc = (float2*)smb;
    int b  = blockIdx.z;
    int ox = blockIdx.x * 32;
    int oy = blockIdx.y * 32;
    int tid = threadIdx.x;

    if (tid < 49) {
        float2 w = g_Kc[b * 98 + (ADJ ? 49 : 0) + tid];
        Kr[tid] = w.x;
        Ki[tid] = w.y;
    }
    for (int i = tid; i < 38 * 38; i += 256) {
        int iy = i / 38, ix = i - iy * 38;
        int gy = oy - 3 + iy, gx = ox - 3 + ix;
        bool in = ((unsigned)gy < 256u) && ((unsigned)gx < 256u);
        if (!ADJ) sr[i] = in ? inR[(size_t)b * IMG + gy * 256 + gx] : 0.0f;
        else      sc[i] = in ? inC[(size_t)b * IMG + gy * 256 + gx] : make_float2(0.f, 0.f);
    }
    __syncthreads();

    int py  = tid >> 3;
    int px0 = (tid & 7) * 4;
    int base = py * 38 + px0;

    float aR[4] = {0.f, 0.f, 0.f, 0.f};
    float aI[4] = {0.f, 0.f, 0.f, 0.f};

    for (int dy = 0; dy < 7; ++dy) {
        int rowo = base + dy * 38;
        if (!ADJ) {
            float v[10];
#pragma unroll
            for (int j = 0; j < 10; ++j) v[j] = sr[rowo + j];
#pragma unroll
            for (int dx = 0; dx < 7; ++dx) {
                float wr = Kr[dy * 7 + dx];
                float wi = Ki[dy * 7 + dx];
#pragma unroll
                for (int k = 0; k < 4; ++k) {
                    aR[k] = fmaf(v[dx + k], wr, aR[k]);
                    aI[k] = fmaf(v[dx + k], wi, aI[k]);
                }
            }
        } else {
            float2 v[10];
#pragma unroll
            for (int j = 0; j < 10; ++j) v[j] = sc[rowo + j];
#pragma unroll
            for (int dx = 0; dx < 7; ++dx) {
                float wr = Kr[dy * 7 + dx];
                float wi = Ki[dy * 7 + dx];
#pragma unroll
                for (int k = 0; k < 4; ++k) {
                    aR[k] = fmaf(v[dx + k].x, wr, fmaf(-v[dx + k].y, wi, aR[k]));
                    aI[k] = fmaf(v[dx + k].x, wi, fmaf(v[dx + k].y, wr, aI[k]));
                }
            }
        }
    }

    int grow = (oy + py) * 256 + ox + px0;
#pragma unroll
    for (int k = 0; k < 4; ++k) {
        int gidx = grow + k;
        float rr = aR[k], ii = aI[k];
        if (!ADJ) {
            float tr = thr[b * IMG + gidx], ti = thi[b * IMG + gidx];
            float nr = rr * tr - ii * ti;
            float ni = rr * ti + ii * tr;
            rr = nr; ii = ni;
        }
        out[(size_t)b * IMG + gidx] = make_float2(rr, ii);
    }
}

// fft2 pass 1: ifftshift on read, forward FFT along x; store k=0..127 only.
// 2 rows/block (128 threads, grid 128 x NB).
__global__ void __launch_bounds__(128)
fft_row_fwd(const int* __restrict__ ep, int iter) {
    if (iter >= get_K(ep)) return;
    __shared__ float2 s[2][256];
    __shared__ float2 tw[192];
    int b = blockIdx.y, t = threadIdx.x, ty = threadIdx.y;
    int y = blockIdx.x * 2 + ty;
    build_tw(tw, ty * 64 + t, -1.0f);
    build_tw(tw, 128 + ty * 64 + t, -1.0f);
    const float2* irow = g_FB + (b * 256 + (y ^ 128)) * 256;
#pragma unroll
    for (int k = 0; k < 4; ++k) {
        int p = t + k * 64;
        s[ty][dr4(p)] = irow[p ^ 128];
    }
    __syncthreads();
    fft256_r4<1, -1>(s[ty], tw, t);
    float2* orow = g_FA + (b * 256 + y) * 256;
    orow[t]      = s[ty][t];
    orow[t + 64] = s[ty][t + 64];
}

// fft2 pass 2: columns 0..127, crop 127x127, accumulate into x.
__global__ void __launch_bounds__(1024)
fft_col_fwd_accum(const int* __restrict__ ep, int iter) {
    if (iter >= get_K(ep)) return;
    __shared__ float2 s[256 * 16];
    __shared__ float2 tw[192];
    int b  = blockIdx.y;
    int tx = threadIdx.x, ty = threadIdx.y;     // 16 x 64
    int tid = ty * 16 + tx;
    int x = blockIdx.x * 16 + tx;
    build_tw(tw, tid, -1.0f);
#pragma unroll
    for (int k = 0; k < 4; ++k) {
        int r = ty + k * 64;
        s[dr4(r) * 16 + tx] = g_FA[(b * 256 + r) * 256 + x];
    }
    __syncthreads();
    fft256_r4<16, -1>(s + tx, tw, ty);
    if (x < 127) {
#pragma unroll
        for (int k = 0; k < 4; ++k) {
            int r = ty + k * 64;
            if (r < 127)
                g_x[b * NN + r * 127 + x] += s[r * 16 + tx].x;
        }
    }
}

// Residual norm.
__global__ void __launch_bounds__(256)
norm_partial(const float* __restrict__ f, const float* __restrict__ kA) {
    __shared__ float sr_s[256], sf_s[256];
    int b = blockIdx.y;
    int row = blockIdx.x * 2 + (threadIdx.x >> 7);
    int col = threadIdx.x & 127;
    float sr = 0.0f, sf = 0.0f;
    if (row < 127 && col < 127) {
        int p = row * 127 + col;
        const float* ka = kA + b * 9;
        const float* xb = g_x + b * NN;
        float s = 0.0f;
        if (row > 0) {
            if (col > 0)   s += ka[0] * xb[p - 128];
            s += ka[1] * xb[p - 127];
            if (col < 126) s += ka[2] * xb[p - 126];
        }
        if (col > 0)   s += ka[3] * xb[p - 1];
        s += ka[4] * xb[p];
        if (col < 126) s += ka[5] * xb[p + 1];
        if (row < 126) {
            if (col > 0)   s += ka[6] * xb[p + 126];
            s += ka[7] * xb[p + 127];
            if (col < 126) s += ka[8] * xb[p + 128];
        }
        float fv = f[b * NN + p];
        float rv = fv - s;
        sr = rv * rv;
        sf = fv * fv;
    }
    sr_s[threadIdx.x] = sr;
    sf_s[threadIdx.x] = sf;
    __syncthreads();
    for (int o = 128; o > 0; o >>= 1) {
        if (threadIdx.x < o) {
            sr_s[threadIdx.x] += sr_s[threadIdx.x + o];
            sf_s[threadIdx.x] += sf_s[threadIdx.x + o];
        }
        __syncthreads();
    }
    if (threadIdx.x == 0) g_part[b * 64 + blockIdx.x] = make_float2(sr_s[0], sf_s[0]);
}

__global__ void norm_final(float* __restrict__ out) {
    __shared__ float sr_s[256], sf_s[256];
    float sr = 0.0f, sf = 0.0f;
#pragma unroll
    for (int k = 0; k < 4; ++k) {
        float2 v = g_part[threadIdx.x + k * 256];
        sr += v.x; sf += v.y;
    }
    sr_s[threadIdx.x] = sr;
    sf_s[threadIdx.x] = sf;
    __syncthreads();
    for (int o = 128; o > 0; o >>= 1) {
        if (threadIdx.x < o) {
            sr_s[threadIdx.x] += sr_s[threadIdx.x + o];
            sf_s[threadIdx.x] += sf_s[threadIdx.x + o];
        }
        __syncthreads();
    }
    if (threadIdx.x == 0) out[0] = sqrtf(sr_s[0] / sf_s[0]);
}

// ---------------- launch ------------------------------------------------------
extern "C" void kernel_launch(void* const* d_in, const int* in_sizes, int n_in,
                              void* d_out, int out_size) {
    (void)in_sizes; (void)n_in; (void)out_size;
    const float* f   = (const float*)d_in[0];
    const float* kA  = (const float*)d_in[1];
    const float* w1r = (const float*)d_in[2];
    const float* w1i = (const float*)d_in[3];
    const float* w2r = (const float*)d_in[4];
    const float* w2i = (const float*)d_in[5];
    const float* w3r = (const float*)d_in[6];
    const float* w3i = (const float*)d_in[7];
    const float* thr = (const float*)d_in[8];
    const float* thi = (const float*)d_in[9];
    const int*   ep  = (const int*)d_in[10];
    float* out = (float*)d_out;

    void *pFA = nullptr, *pFB = nullptr;
    cudaGetSymbolAddress(&pFA, g_FA);
    cudaGetSymbolAddress(&pFB, g_FB);

    compose_kernels<<<NB, 64>>>(w1r, w1i, w2r, w2i, w3r, w3i);

    dim3 jg(4, 4, NB);
    for (int it = 0; it < 3; ++it) {
        jacobi_tile<<<jg, 512>>>(f, kA, ep, it, 0, it == 0 ? 1 : 0);
        jacobi_tile<<<jg, 512>>>(f, kA, ep, it, 1, 0);
        fft_row_expand<<<dim3(16, NB), dim3(64, 4)>>>(ep, it);
        fft_col_inv<<<dim3(8, NB), dim3(16, 64)>>>(ep, it);
        conv7<false><<<dim3(8, 8, NB), 256>>>(
            (const float*)pFB, nullptr, (float2*)pFA, thr, thi, ep, it);
        conv7<true><<<dim3(8, 8, NB), 256>>>(
            nullptr, (const float2*)pFA, (float2*)pFB, nullptr, nullptr, ep, it);
        fft_row_fwd<<<dim3(128, NB), dim3(64, 2)>>>(ep, it);
        fft_col_fwd_accum<<<dim3(8, NB), dim3(16, 64)>>>(ep, it);
    }

    norm_partial<<<dim3(64, NB), 256>>>(f, kA);
    norm_final<<<1, 256>>>(out);
}

// round 16
// speedup vs baseline: 1.2808x; 1.0950x over previous
#include <cuda_runtime.h>
#include <math.h>

#define NB   16
#define NI   127
#define NN   16129      // 127*127
#define IMG  65536      // 256*256
#define TS   32
#define HL2  11
#define LT2  54         // TS + 2*HL2
#define LTN  2916       // LT2*LT2

typedef unsigned long long u64;

// ---------------- scratch (static device globals) ----------------------------
static __device__ float  g_x[NB * NN];
static __device__ float  g_r[NB * NN];
static __device__ float2 g_FA[NB * IMG];
static __device__ float2 g_FB[NB * IMG];   // also reused as float (real) buffer
static __device__ float2 g_Kc[NB * 98];    // composed 7x7 kernels: [49 fwd | 49 adj]
static __device__ float2 g_Wa[NB * NN];    // adjoint transfer function, 127x127 crop
static __device__ float2 g_part[1024];

// ---------------- misc helpers ------------------------------------------------
__device__ __forceinline__ int get_K(const int* ep) {
    int ei = *ep;
    int e;
    if (ei > 0 && ei <= 1000000) {
        e = ei;
    } else {
        float ff = __int_as_float(ei);
        e = (ff >= 1.0f && ff <= 1000000.0f) ? (int)ff : 120;
    }
    int K = (e - 1) / 40 + 1;
    if (K > 10) K = 10;
    if (K < 1)  K = 1;
    return K;
}

__device__ __forceinline__ int dr4(int p) {
    return ((p & 3) << 6) | (((p >> 2) & 3) << 4) | (((p >> 4) & 3) << 2) | ((p >> 6) & 3);
}

__device__ __forceinline__ float2 cmulf(float2 a, float2 b) {
    return make_float2(a.x * b.x - a.y * b.y, a.x * b.y + a.y * b.x);
}

__device__ __forceinline__ void build_tw(float2* tw, int tid, float sign) {
    if (tid < 192) {
        float s, c;
        __sincosf(sign * 6.283185307179586f * (float)tid * (1.0f / 256.0f), &s, &c);
        tw[tid] = make_float2(c, s);
    }
}

// Radix-4 256-pt DIT FFT, input base-4 digit-reversed, output natural.
template <int STRIDE, int SGN>
__device__ __forceinline__ void fft256_r4(float2* s, const float2* tw, int t) {
#pragma unroll
    for (int st = 0; st < 4; ++st) {
        int L    = 1 << (2 * st);
        int k    = t & (L - 1);
        int g    = t >> (2 * st);
        int i0   = g * 4 * L + k;
        int step = 64 >> (2 * st);
        float2 a = s[i0 * STRIDE];
        float2 b = s[(i0 + L) * STRIDE];
        float2 c = s[(i0 + 2 * L) * STRIDE];
        float2 d = s[(i0 + 3 * L) * STRIDE];
        b = cmulf(b, tw[k * step]);
        c = cmulf(c, tw[2 * k * step]);
        d = cmulf(d, tw[3 * k * step]);
        float2 t0 = make_float2(a.x + c.x, a.y + c.y);
        float2 t1 = make_float2(a.x - c.x, a.y - c.y);
        float2 t2 = make_float2(b.x + d.x, b.y + d.y);
        float2 t3 = make_float2(b.x - d.x, b.y - d.y);
        float2 rot = make_float2(-(float)SGN * t3.y, (float)SGN * t3.x);
        s[i0 * STRIDE]           = make_float2(t0.x + t2.x, t0.y + t2.y);
        s[(i0 + L) * STRIDE]     = make_float2(t1.x + rot.x, t1.y + rot.y);
        s[(i0 + 2 * L) * STRIDE] = make_float2(t0.x - t2.x, t0.y - t2.y);
        s[(i0 + 3 * L) * STRIDE] = make_float2(t1.x - rot.x, t1.y - rot.y);
        __syncthreads();
    }
}

// ---------------- kernels ----------------------------------------------------
// One-time: compose the 3-conv stacks into per-sample 7x7 correlation kernels.
__global__ void __launch_bounds__(64)
compose_kernels(const float* __restrict__ w1r, const float* __restrict__ w1i,
                const float* __restrict__ w2r, const float* __restrict__ w2i,
                const float* __restrict__ w3r, const float* __restrict__ w3i) {
    __shared__ float s1r[36], s1i[36], s2r[144], s2i[144], s3r[36], s3i[36];
    int b = blockIdx.x;
    int t = threadIdx.x;
    if (t < 36) { s1r[t] = w1r[b * 36 + t]; s1i[t] = w1i[b * 36 + t]; }
    if (t < 36) { s3r[t] = w3r[b * 36 + t]; s3i[t] = w3i[b * 36 + t]; }
    for (int i = t; i < 144; i += 64) { s2r[i] = w2r[b * 144 + i]; s2i[i] = w2i[b * 144 + i]; }
    __syncthreads();
    if (t >= 49) return;
    int my = t / 7 - 3, mx = t % 7 - 3;
    float fr = 0.f, fi = 0.f, ar = 0.f, ai = 0.f;
    for (int c2 = 0; c2 < 4; ++c2)
    for (int c1 = 0; c1 < 4; ++c1)
    for (int j = 0; j < 9; ++j) {
        int jy = j / 3 - 1, jx = j % 3 - 1;
        for (int k = 0; k < 9; ++k) {
            int ky = k / 3 - 1, kx = k % 3 - 1;
            int ly = my - jy - ky, lx = mx - jx - kx;
            if (ly < -1 || ly > 1 || lx < -1 || lx > 1) continue;
            int l = (ly + 1) * 3 + (lx + 1);
            {
                float xr = s3r[c2 * 9 + j],            xi = s3i[c2 * 9 + j];
                float yr = s2r[(c2 * 4 + c1) * 9 + k], yi = s2i[(c2 * 4 + c1) * 9 + k];
                float zr = s1r[c1 * 9 + l],            zi = s1i[c1 * 9 + l];
                float pr = xr * yr - xi * yi, pi = xr * yi + xi * yr;
                fr += pr * zr - pi * zi;
                fi += pr * zi + pi * zr;
            }
            {
                int jT = (j % 3) * 3 + j / 3;
                int kT = (k % 3) * 3 + k / 3;
                int lT = (l % 3) * 3 + l / 3;
                float xr = s1r[c2 * 9 + jT],            xi = -s1i[c2 * 9 + jT];
                float yr = s2r[(c1 * 4 + c2) * 9 + kT], yi = -s2i[(c1 * 4 + c2) * 9 + kT];
                float zr = s3r[c1 * 9 + lT],            zi = -s3i[c1 * 9 + lT];
                float pr = xr * yr - xi * yi, pi = xr * yi + xi * yr;
                ar += pr * zr - pi * zi;
                ai += pr * zi + pi * zr;
            }
        }
    }
    g_Kc[b * 98 + t]      = make_float2(fr, fi);
    g_Kc[b * 98 + 49 + t] = make_float2(ar, ai);
}

// One-time: Wa[k,l] = sum_m Ka[m] * exp(+2pi*i*(k*(my-3)+l*(mx-3))/256), k,l<127.
__global__ void __launch_bounds__(256)
build_Wa() {
    __shared__ float2 T[7][127];
    __shared__ float2 Ks[49];
    int b = blockIdx.x, t = threadIdx.x;
    if (t < 49) Ks[t] = g_Kc[b * 98 + 49 + t];
    __syncthreads();
    if (t < 127) {
        float sx, cx;
        __sincosf(6.283185307179586f * (float)t * (1.0f / 256.0f), &sx, &cx);
        float2 base = make_float2(cx, sx);
        float2 p[7];
        p[3] = make_float2(1.f, 0.f);
        p[4] = base;
        p[5] = cmulf(base, base);
        p[6] = cmulf(p[5], base);
        p[2] = make_float2(p[4].x, -p[4].y);
        p[1] = make_float2(p[5].x, -p[5].y);
        p[0] = make_float2(p[6].x, -p[6].y);
#pragma unroll
        for (int dy = 0; dy < 7; ++dy) {
            float2 acc = make_float2(0.f, 0.f);
#pragma unroll
            for (int dx = 0; dx < 7; ++dx) {
                float2 kv = Ks[dy * 7 + dx];
                float2 ph = p[dx];
                acc.x += kv.x * ph.x - kv.y * ph.y;
                acc.y += kv.x * ph.y + kv.y * ph.x;
            }
            T[dy][t] = acc;
        }
    }
    __syncthreads();
    for (int o = t; o < NN; o += 256) {
        int r = o / 127, x = o - r * 127;
        float sr_, cr_;
        __sincosf(6.283185307179586f * (float)r * (1.0f / 256.0f), &sr_, &cr_);
        float2 base = make_float2(cr_, sr_);
        float2 q[7];
        q[3] = make_float2(1.f, 0.f);
        q[4] = base;
        q[5] = cmulf(base, base);
        q[6] = cmulf(q[5], base);
        q[2] = make_float2(q[4].x, -q[4].y);
        q[1] = make_float2(q[5].x, -q[5].y);
        q[0] = make_float2(q[6].x, -q[6].y);
        float2 acc = make_float2(0.f, 0.f);
#pragma unroll
        for (int dy = 0; dy < 7; ++dy) {
            float2 v = cmulf(q[dy], T[dy][x]);
            acc.x += v.x; acc.y += v.y;
        }
        g_Wa[b * NN + o] = acc;
    }
}

// Sweep-chunked Jacobi: 10 sweeps/launch on 54x54 tiles (halo 11), 512 threads.
__global__ void __launch_bounds__(512)
jacobi_tile(const float* __restrict__ f, const float* __restrict__ kA,
            const int* __restrict__ ep, int iter, int final_, int zero) {
    if (iter >= get_K(ep)) return;
    __shared__ float xs0[LTN], xs1[LTN], fs[LTN];
    int b  = blockIdx.z;
    int ox = blockIdx.x * TS - HL2;
    int oy = blockIdx.y * TS - HL2;
    int tid = threadIdx.x;
    const float* ka = kA + b * 9;
    float k0 = ka[0], k1 = ka[1], k2 = ka[2], k3 = ka[3], k4 = ka[4];
    float k5 = ka[5], k6 = ka[6], k7 = ka[7], k8 = ka[8];
    float tau = 0.5f / k4;

    int  iyk[6], ixk[6];
    bool okk[6], domk[6];
#pragma unroll
    for (int k = 0; k < 6; ++k) {
        int p = tid + k * 512;
        bool ok = p < LTN;
        int iy = 0, ix = 0;
        if (ok) { iy = p / LT2; ix = p - iy * LT2; }
        int gy = oy + iy, gx = ox + ix;
        bool dom = ok && ((unsigned)gy < 127u) && ((unsigned)gx < 127u);
        if (ok) {
            xs0[p] = (dom && !zero) ? g_x[b * NN + gy * 127 + gx] : 0.0f;
            fs[p]  = dom ? f[b * NN + gy * 127 + gx] : 0.0f;
        }
        iyk[k] = iy; ixk[k] = ix; okk[k] = ok; domk[k] = dom;
    }
    __syncthreads();

    float* cur = xs0;
    float* nxt = xs1;
#pragma unroll
    for (int s = 0; s < 10; ++s) {
        int a = s + 1;
#pragma unroll
        for (int k = 0; k < 6; ++k) {
            if (okk[k]) {
                int p = tid + k * 512;
                float nv = cur[p];
                int iy = iyk[k], ix = ixk[k];
                if (domk[k] && iy >= a && iy < LT2 - a && ix >= a && ix < LT2 - a) {
                    float ax = k0 * cur[p - LT2 - 1] + k1 * cur[p - LT2] + k2 * cur[p - LT2 + 1]
                             + k3 * cur[p - 1]       + k4 * cur[p]       + k5 * cur[p + 1]
                             + k6 * cur[p + LT2 - 1] + k7 * cur[p + LT2] + k8 * cur[p + LT2 + 1];
                    nv = cur[p] + tau * (fs[p] - ax);
                }
                nxt[p] = nv;
            }
        }
        __syncthreads();
        float* tsw = cur; cur = nxt; nxt = tsw;
    }

#pragma unroll
    for (int k = 0; k < 2; ++k) {
        int p2 = tid + k * 512;
        int py = p2 >> 5, px = p2 & 31;
        int iy = HL2 + py, ix = HL2 + px;
        int gy = oy + iy, gx = ox + ix;
        if (((unsigned)gy < 127u) && ((unsigned)gx < 127u)) {
            int i = iy * LT2 + ix;
            g_x[b * NN + gy * 127 + gx] = cur[i];
            if (final_) {
                float ax = k0 * cur[i - LT2 - 1] + k1 * cur[i - LT2] + k2 * cur[i - LT2 + 1]
                         + k3 * cur[i - 1]       + k4 * cur[i]       + k5 * cur[i + 1]
                         + k6 * cur[i + LT2 - 1] + k7 * cur[i + LT2] + k8 * cur[i + LT2 + 1];
                g_r[b * NN + gy * 127 + gx] = fs[i] - ax;
            }
        }
    }
}

// ifft2 pass 1, packed: two real expanded rows per complex FFT.
__global__ void __launch_bounds__(256)
fft_row_expand(const int* __restrict__ ep, int iter) {
    if (iter >= get_K(ep)) return;
    __shared__ float2 s[4][256];
    __shared__ float2 tw[192];
    int b = blockIdx.y, t = threadIdx.x, ty = threadIdx.y;
    int j = blockIdx.x * 4 + ty;                // 0..63
    int y1 = 2 * j + 1;
    int y2 = 2 * j + 2;
    bool two = (j < 63);
    build_tw(tw, ty * 64 + t, 1.0f);
    const float* r1 = g_r + (b * NN + (y1 - 1) * 127);
    const float* r2 = g_r + (b * NN + (two ? (y2 - 1) : 0) * 127);
#pragma unroll
    for (int k = 0; k < 4; ++k) {
        int p = t + k * 64;
        float v1 = 0.0f, v2 = 0.0f;
        if (p >= 1 && p <= 127) {
            v1 = r1[p - 1];
            if (two) v2 = r2[p - 1];
        } else if (p >= 129) {
            v1 = -r1[255 - p];
            if (two) v2 = -r2[255 - p];
        }
        s[ty][dr4(p)] = make_float2(v1, v2);
    }
    __syncthreads();
    fft256_r4<1, 1>(s[ty], tw, t);
    float2* base = g_FA + (size_t)b * IMG;
#pragma unroll
    for (int k = 0; k < 2; ++k) {
        int kk = t + k * 64;
        float2 Zk = s[ty][kk];
        float2 Zm = s[ty][(256 - kk) & 255];
        float sr_ = Zk.x + Zm.x, si_ = Zk.y - Zm.y;
        float dr_ = Zk.x - Zm.x, di_ = Zk.y + Zm.y;
        float2 F1 = make_float2(0.5f * sr_, 0.5f * si_);
        float2 F2 = make_float2(0.5f * di_, -0.5f * dr_);
        base[y1 * 256 + kk]         = F1;
        base[(256 - y1) * 256 + kk] = make_float2(-F1.x, -F1.y);
        if (two) {
            base[y2 * 256 + kk]         = F2;
            base[(256 - y2) * 256 + kk] = make_float2(-F2.x, -F2.y);
        }
    }
    if (blockIdx.x == 0 && ty == 0) {
#pragma unroll
        for (int k = 0; k < 2; ++k) {
            int kk = t + k * 64;
            base[kk]             = make_float2(0.f, 0.f);
            base[128 * 256 + kk] = make_float2(0.f, 0.f);
        }
    }
}

// ifft2 pass 2: columns 0..127; output purely REAL into g_FB (float view).
__global__ void __launch_bounds__(1024)
fft_col_inv(const int* __restrict__ ep, int iter) {
    if (iter >= get_K(ep)) return;
    __shared__ float2 s[256 * 16];
    __shared__ float2 tw[192];
    int b  = blockIdx.y;
    int tx = threadIdx.x, ty = threadIdx.y;     // 16 x 64
    int tid = ty * 16 + tx;
    int x = blockIdx.x * 16 + tx;               // 0..127
    build_tw(tw, tid, 1.0f);
#pragma unroll
    for (int k = 0; k < 4; ++k) {
        int r = ty + k * 64;
        s[dr4(r) * 16 + tx] = g_FA[(b * 256 + r) * 256 + x];
    }
    __syncthreads();
    fft256_r4<16, 1>(s + tx, tw, ty);
    const float sc = 1.0f / 65536.0f;
    float* FB = (float*)g_FB;
#pragma unroll
    for (int k = 0; k < 4; ++k) {
        int r = ty + k * 64;
        float val = s[r * 16 + tx].x * sc;
        int n2 = (r ^ 128);
        float* row = FB + (size_t)b * IMG + n2 * 256;
        if (x == 0) {
            row[128] = val;
            row[0]   = 0.0f;
        } else {
            row[x + 128] = val;
            row[128 - x] = -val;
        }
    }
}

// Composed forward 7x7 correlation, real input, *theta, write g_FA.
__global__ void __launch_bounds__(256)
conv7(const float* __restrict__ inR, float2* __restrict__ out,
      const float* __restrict__ thr, const float* __restrict__ thi,
      const int* __restrict__ ep, int iter) {
    if (iter >= get_K(ep)) return;
    __shared__ float sr[38 * 38];
    __shared__ float Kr[49], Ki[49];
    int b  = blockIdx.z;
    int ox = blockIdx.x * 32;
    int oy = blockIdx.y * 32;
    int tid = threadIdx.x;

    if (tid < 49) {
        float2 w = g_Kc[b * 98 + tid];
        Kr[tid] = w.x;
        Ki[tid] = w.y;
    }
    for (int i = tid; i < 38 * 38; i += 256) {
        int iy = i / 38, ix = i - iy * 38;
        int gy = oy - 3 + iy, gx = ox - 3 + ix;
        bool in = ((unsigned)gy < 256u) && ((unsigned)gx < 256u);
        sr[i] = in ? inR[(size_t)b * IMG + gy * 256 + gx] : 0.0f;
    }
    __syncthreads();

    int py  = tid >> 3;
    int px0 = (tid & 7) * 4;
    int base = py * 38 + px0;

    float aR[4] = {0.f, 0.f, 0.f, 0.f};
    float aI[4] = {0.f, 0.f, 0.f, 0.f};

    for (int dy = 0; dy < 7; ++dy) {
        int rowo = base + dy * 38;
        float v[10];
#pragma unroll
        for (int j = 0; j < 10; ++j) v[j] = sr[rowo + j];
#pragma unroll
        for (int dx = 0; dx < 7; ++dx) {
            float wr = Kr[dy * 7 + dx];
            float wi = Ki[dy * 7 + dx];
#pragma unroll
            for (int k = 0; k < 4; ++k) {
                aR[k] = fmaf(v[dx + k], wr, aR[k]);
                aI[k] = fmaf(v[dx + k], wi, aI[k]);
            }
        }
    }

    int grow = (oy + py) * 256 + ox + px0;
#pragma unroll
    for (int k = 0; k < 4; ++k) {
        int gidx = grow + k;
        float rr = aR[k], ii = aI[k];
        float tr = thr[b * IMG + gidx], ti = thi[b * IMG + gidx];
        float nr = rr * tr - ii * ti;
        float ni = rr * ti + ii * tr;
        out[(size_t)b * IMG + gidx] = make_float2(nr, ni);
    }
}

// fft2 pass 1: ifftshift on read (from g_FA), forward FFT along x; write g_FB.
__global__ void __launch_bounds__(128)
fft_row_fwd(const int* __restrict__ ep, int iter) {
    if (iter >= get_K(ep)) return;
    __shared__ float2 s[2][256];
    __shared__ float2 tw[192];
    int b = blockIdx.y, t = threadIdx.x, ty = threadIdx.y;
    int y = blockIdx.x * 2 + ty;
    build_tw(tw, ty * 64 + t, -1.0f);
    build_tw(tw, 128 + ty * 64 + t, -1.0f);
    const float2* irow = g_FA + (b * 256 + (y ^ 128)) * 256;
#pragma unroll
    for (int k = 0; k < 4; ++k) {
        int p = t + k * 64;
        s[ty][dr4(p)] = irow[p ^ 128];
    }
    __syncthreads();
    fft256_r4<1, -1>(s[ty], tw, t);
    float2* orow = g_FB + (b * 256 + y) * 256;
    orow[t]      = s[ty][t];
    orow[t + 64] = s[ty][t + 64];
}

// fft2 pass 2: columns 0..127 (from g_FB), col FFT, multiply by Wa (adjoint
// conv as circular transfer function), take real, accumulate into x.
__global__ void __launch_bounds__(1024)
fft_col_fwd_accum(const int* __restrict__ ep, int iter) {
    if (iter >= get_K(ep)) return;
    __shared__ float2 s[256 * 16];
    __shared__ float2 tw[192];
    int b  = blockIdx.y;
    int tx = threadIdx.x, ty = threadIdx.y;     // 16 x 64
    int tid = ty * 16 + tx;
    int x = blockIdx.x * 16 + tx;
    build_tw(tw, tid, -1.0f);
#pragma unroll
    for (int k = 0; k < 4; ++k) {
        int r = ty + k * 64;
        s[dr4(r) * 16 + tx] = g_FB[(b * 256 + r) * 256 + x];
    }
    __syncthreads();
    fft256_r4<16, -1>(s + tx, tw, ty);
    if (x < 127) {
#pragma unroll
        for (int k = 0; k < 4; ++k) {
            int r = ty + k * 64;
            if (r < 127) {
                float2 S = s[r * 16 + tx];
                float2 w = g_Wa[b * NN + r * 127 + x];
                g_x[b * NN + r * 127 + x] += w.x * S.x - w.y * S.y;
            }
        }
    }
}

// Residual norm.
__global__ void __launch_bounds__(256)
norm_partial(const float* __restrict__ f, const float* __restrict__ kA) {
    __shared__ float sr_s[256], sf_s[256];
    int b = blockIdx.y;
    int row = blockIdx.x * 2 + (threadIdx.x >> 7);
    int col = threadIdx.x & 127;
    float sr = 0.0f, sf = 0.0f;
    if (row < 127 && col < 127) {
        int p = row * 127 + col;
        const float* ka = kA + b * 9;
        const float* xb = g_x + b * NN;
        float s = 0.0f;
        if (row > 0) {
            if (col > 0)   s += ka[0] * xb[p - 128];
            s += ka[1] * xb[p - 127];
            if (col < 126) s += ka[2] * xb[p - 126];
        }
        if (col > 0)   s += ka[3] * xb[p - 1];
        s += ka[4] * xb[p];
        if (col < 126) s += ka[5] * xb[p + 1];
        if (row < 126) {
            if (col > 0)   s += ka[6] * xb[p + 126];
            s += ka[7] * xb[p + 127];
            if (col < 126) s += ka[8] * xb[p + 128];
        }
        float fv = f[b * NN + p];
        float rv = fv - s;
        sr = rv * rv;
        sf = fv * fv;
    }
    sr_s[threadIdx.x] = sr;
    sf_s[threadIdx.x] = sf;
    __syncthreads();
    for (int o = 128; o > 0; o >>= 1) {
        if (threadIdx.x < o) {
            sr_s[threadIdx.x] += sr_s[threadIdx.x + o];
            sf_s[threadIdx.x] += sf_s[threadIdx.x + o];
        }
        __syncthreads();
    }
    if (threadIdx.x == 0) g_part[b * 64 + blockIdx.x] = make_float2(sr_s[0], sf_s[0]);
}

__global__ void norm_final(float* __restrict__ out) {
    __shared__ float sr_s[256], sf_s[256];
    float sr = 0.0f, sf = 0.0f;
#pragma unroll
    for (int k = 0; k < 4; ++k) {
        float2 v = g_part[threadIdx.x + k * 256];
        sr += v.x; sf += v.y;
    }
    sr_s[threadIdx.x] = sr;
    sf_s[threadIdx.x] = sf;
    __syncthreads();
    for (int o = 128; o > 0; o >>= 1) {
        if (threadIdx.x < o) {
            sr_s[threadIdx.x] += sr_s[threadIdx.x + o];
            sf_s[threadIdx.x] += sf_s[threadIdx.x + o];
        }
        __syncthreads();
    }
    if (threadIdx.x == 0) out[0] = sqrtf(sr_s[0] / sf_s[0]);
}

// ---------------- launch ------------------------------------------------------
extern "C" void kernel_launch(void* const* d_in, const int* in_sizes, int n_in,
                              void* d_out, int out_size) {
    (void)in_sizes; (void)n_in; (void)out_size;
    const float* f   = (const float*)d_in[0];
    const float* kA  = (const float*)d_in[1];
    const float* w1r = (const float*)d_in[2];
    const float* w1i = (const float*)d_in[3];
    const float* w2r = (const float*)d_in[4];
    const float* w2i = (const float*)d_in[5];
    const float* w3r = (const float*)d_in[6];
    const float* w3i = (const float*)d_in[7];
    const float* thr = (const float*)d_in[8];
    const float* thi = (const float*)d_in[9];
    const int*   ep  = (const int*)d_in[10];
    float* out = (float*)d_out;

    void *pFA = nullptr, *pFB = nullptr;
    cudaGetSymbolAddress(&pFA, g_FA);
    cudaGetSymbolAddress(&pFB, g_FB);

    compose_kernels<<<NB, 64>>>(w1r, w1i, w2r, w2i, w3r, w3i);
    build_Wa<<<NB, 256>>>();

    dim3 jg(4, 4, NB);
    for (int it = 0; it < 3; ++it) {
        jacobi_tile<<<jg, 512>>>(f, kA, ep, it, 0, it == 0 ? 1 : 0);
        jacobi_tile<<<jg, 512>>>(f, kA, ep, it, 1, 0);
        fft_row_expand<<<dim3(16, NB), dim3(64, 4)>>>(ep, it);
        fft_col_inv<<<dim3(8, NB), dim3(16, 64)>>>(ep, it);
        conv7<<<dim3(8, 8, NB), 256>>>(
            (const float*)pFB, (float2*)pFA, thr, thi, ep, it);
        fft_row_fwd<<<dim3(128, NB), dim3(64, 2)>>>(ep, it);
        fft_col_fwd_accum<<<dim3(8, NB), dim3(16, 64)>>>(ep, it);
    }

    norm_partial<<<dim3(64, NB), 256>>>(f, kA);
    norm_final<<<1, 256>>>(out);
}

// round 17
// speedup vs baseline: 1.2874x; 1.0051x over previous
#include <cuda_runtime.h>
#include <math.h>

#define NB   16
#define NI   127
#define NN   16129      // 127*127
#define IMG  65536      // 256*256
#define TS   32
#define HL2  11
#define LT2  54         // TS + 2*HL2
#define LTN  2916       // LT2*LT2

typedef unsigned long long u64;

// ---------------- scratch (static device globals) ----------------------------
static __device__ float  g_x[NB * NN];
static __device__ float  g_r[NB * NN];
static __device__ float2 g_FA[NB * IMG];
static __device__ float2 g_FB[NB * IMG];   // also reused as float (real) buffer
static __device__ float2 g_Kc[NB * 98];    // composed 7x7 kernels: [49 fwd | 49 adj]
static __device__ float2 g_Wa[NB * NN];    // adjoint transfer function, 127x127 crop
static __device__ float2 g_part[1024];

// ---------------- misc helpers ------------------------------------------------
__device__ __forceinline__ int get_K(const int* ep) {
    int ei = *ep;
    int e;
    if (ei > 0 && ei <= 1000000) {
        e = ei;
    } else {
        float ff = __int_as_float(ei);
        e = (ff >= 1.0f && ff <= 1000000.0f) ? (int)ff : 120;
    }
    int K = (e - 1) / 40 + 1;
    if (K > 10) K = 10;
    if (K < 1)  K = 1;
    return K;
}

__device__ __forceinline__ int dr4(int p) {
    return ((p & 3) << 6) | (((p >> 2) & 3) << 4) | (((p >> 4) & 3) << 2) | ((p >> 6) & 3);
}

__device__ __forceinline__ float2 cmulf(float2 a, float2 b) {
    return make_float2(a.x * b.x - a.y * b.y, a.x * b.y + a.y * b.x);
}

__device__ __forceinline__ void build_tw(float2* tw, int tid, float sign) {
    if (tid < 192) {
        float s, c;
        __sincosf(sign * 6.283185307179586f * (float)tid * (1.0f / 256.0f), &s, &c);
        tw[tid] = make_float2(c, s);
    }
}

// Radix-4 256-pt DIT FFT, input base-4 digit-reversed, output natural.
template <int STRIDE, int SGN>
__device__ __forceinline__ void fft256_r4(float2* s, const float2* tw, int t) {
#pragma unroll
    for (int st = 0; st < 4; ++st) {
        int L    = 1 << (2 * st);
        int k    = t & (L - 1);
        int g    = t >> (2 * st);
        int i0   = g * 4 * L + k;
        int step = 64 >> (2 * st);
        float2 a = s[i0 * STRIDE];
        float2 b = s[(i0 + L) * STRIDE];
        float2 c = s[(i0 + 2 * L) * STRIDE];
        float2 d = s[(i0 + 3 * L) * STRIDE];
        b = cmulf(b, tw[k * step]);
        c = cmulf(c, tw[2 * k * step]);
        d = cmulf(d, tw[3 * k * step]);
        float2 t0 = make_float2(a.x + c.x, a.y + c.y);
        float2 t1 = make_float2(a.x - c.x, a.y - c.y);
        float2 t2 = make_float2(b.x + d.x, b.y + d.y);
        float2 t3 = make_float2(b.x - d.x, b.y - d.y);
        float2 rot = make_float2(-(float)SGN * t3.y, (float)SGN * t3.x);
        s[i0 * STRIDE]           = make_float2(t0.x + t2.x, t0.y + t2.y);
        s[(i0 + L) * STRIDE]     = make_float2(t1.x + rot.x, t1.y + rot.y);
        s[(i0 + 2 * L) * STRIDE] = make_float2(t0.x - t2.x, t0.y - t2.y);
        s[(i0 + 3 * L) * STRIDE] = make_float2(t1.x - rot.x, t1.y - rot.y);
        __syncthreads();
    }
}

// ---------------- kernels ----------------------------------------------------
// One-time: compose the 3-conv stacks into per-sample 7x7 correlation kernels.
__global__ void __launch_bounds__(64)
compose_kernels(const float* __restrict__ w1r, const float* __restrict__ w1i,
                const float* __restrict__ w2r, const float* __restrict__ w2i,
                const float* __restrict__ w3r, const float* __restrict__ w3i) {
    __shared__ float s1r[36], s1i[36], s2r[144], s2i[144], s3r[36], s3i[36];
    int b = blockIdx.x;
    int t = threadIdx.x;
    if (t < 36) { s1r[t] = w1r[b * 36 + t]; s1i[t] = w1i[b * 36 + t]; }
    if (t < 36) { s3r[t] = w3r[b * 36 + t]; s3i[t] = w3i[b * 36 + t]; }
    for (int i = t; i < 144; i += 64) { s2r[i] = w2r[b * 144 + i]; s2i[i] = w2i[b * 144 + i]; }
    __syncthreads();
    if (t >= 49) return;
    int my = t / 7 - 3, mx = t % 7 - 3;
    float fr = 0.f, fi = 0.f, ar = 0.f, ai = 0.f;
    for (int c2 = 0; c2 < 4; ++c2)
    for (int c1 = 0; c1 < 4; ++c1)
    for (int j = 0; j < 9; ++j) {
        int jy = j / 3 - 1, jx = j % 3 - 1;
        for (int k = 0; k < 9; ++k) {
            int ky = k / 3 - 1, kx = k % 3 - 1;
            int ly = my - jy - ky, lx = mx - jx - kx;
            if (ly < -1 || ly > 1 || lx < -1 || lx > 1) continue;
            int l = (ly + 1) * 3 + (lx + 1);
            {
                float xr = s3r[c2 * 9 + j],            xi = s3i[c2 * 9 + j];
                float yr = s2r[(c2 * 4 + c1) * 9 + k], yi = s2i[(c2 * 4 + c1) * 9 + k];
                float zr = s1r[c1 * 9 + l],            zi = s1i[c1 * 9 + l];
                float pr = xr * yr - xi * yi, pi = xr * yi + xi * yr;
                fr += pr * zr - pi * zi;
                fi += pr * zi + pi * zr;
            }
            {
                int jT = (j % 3) * 3 + j / 3;
                int kT = (k % 3) * 3 + k / 3;
                int lT = (l % 3) * 3 + l / 3;
                float xr = s1r[c2 * 9 + jT],            xi = -s1i[c2 * 9 + jT];
                float yr = s2r[(c1 * 4 + c2) * 9 + kT], yi = -s2i[(c1 * 4 + c2) * 9 + kT];
                float zr = s3r[c1 * 9 + lT],            zi = -s3i[c1 * 9 + lT];
                float pr = xr * yr - xi * yi, pi = xr * yi + xi * yr;
                ar += pr * zr - pi * zi;
                ai += pr * zi + pi * zr;
            }
        }
    }
    g_Kc[b * 98 + t]      = make_float2(fr, fi);
    g_Kc[b * 98 + 49 + t] = make_float2(ar, ai);
}

// One-time: Wa[k,l] = sum_m Ka[m] * exp(+2pi*i*(k*(my-3)+l*(mx-3))/256), k,l<127.
__global__ void __launch_bounds__(256)
build_Wa() {
    __shared__ float2 T[7][127];
    __shared__ float2 Ks[49];
    int b = blockIdx.x, t = threadIdx.x;
    if (t < 49) Ks[t] = g_Kc[b * 98 + 49 + t];
    __syncthreads();
    if (t < 127) {
        float sx, cx;
        __sincosf(6.283185307179586f * (float)t * (1.0f / 256.0f), &sx, &cx);
        float2 base = make_float2(cx, sx);
        float2 p[7];
        p[3] = make_float2(1.f, 0.f);
        p[4] = base;
        p[5] = cmulf(base, base);
        p[6] = cmulf(p[5], base);
        p[2] = make_float2(p[4].x, -p[4].y);
        p[1] = make_float2(p[5].x, -p[5].y);
        p[0] = make_float2(p[6].x, -p[6].y);
#pragma unroll
        for (int dy = 0; dy < 7; ++dy) {
            float2 acc = make_float2(0.f, 0.f);
#pragma unroll
            for (int dx = 0; dx < 7; ++dx) {
                float2 kv = Ks[dy * 7 + dx];
                float2 ph = p[dx];
                acc.x += kv.x * ph.x - kv.y * ph.y;
                acc.y += kv.x * ph.y + kv.y * ph.x;
            }
            T[dy][t] = acc;
        }
    }
    __syncthreads();
    for (int o = t; o < NN; o += 256) {
        int r = o / 127, x = o - r * 127;
        float sr_, cr_;
        __sincosf(6.283185307179586f * (float)r * (1.0f / 256.0f), &sr_, &cr_);
        float2 base = make_float2(cr_, sr_);
        float2 q[7];
        q[3] = make_float2(1.f, 0.f);
        q[4] = base;
        q[5] = cmulf(base, base);
        q[6] = cmulf(q[5], base);
        q[2] = make_float2(q[4].x, -q[4].y);
        q[1] = make_float2(q[5].x, -q[5].y);
        q[0] = make_float2(q[6].x, -q[6].y);
        float2 acc = make_float2(0.f, 0.f);
#pragma unroll
        for (int dy = 0; dy < 7; ++dy) {
            float2 v = cmulf(q[dy], T[dy][x]);
            acc.x += v.x; acc.y += v.y;
        }
        g_Wa[b * NN + o] = acc;
    }
}

// Sweep-chunked Jacobi with dead-zone elimination: both buffers initialized,
// inactive elements never written (depth-hoisted activity test).
__global__ void __launch_bounds__(512)
jacobi_tile(const float* __restrict__ f, const float* __restrict__ kA,
            const int* __restrict__ ep, int iter, int final_, int zero) {
    if (iter >= get_K(ep)) return;
    __shared__ float xs0[LTN], xs1[LTN], fs[LTN];
    int b  = blockIdx.z;
    int ox = blockIdx.x * TS - HL2;
    int oy = blockIdx.y * TS - HL2;
    int tid = threadIdx.x;
    const float* ka = kA + b * 9;
    float k0 = ka[0], k1 = ka[1], k2 = ka[2], k3 = ka[3], k4 = ka[4];
    float k5 = ka[5], k6 = ka[6], k7 = ka[7], k8 = ka[8];
    float tau = 0.5f / k4;

    int dk[6];
#pragma unroll
    for (int k = 0; k < 6; ++k) {
        int p = tid + k * 512;
        bool ok = p < LTN;
        int iy = 0, ix = 0;
        if (ok) { iy = p / LT2; ix = p - iy * LT2; }
        int gy = oy + iy, gx = ox + ix;
        bool dom = ok && ((unsigned)gy < 127u) && ((unsigned)gx < 127u);
        int d = 0;
        if (dom) {
            d = min(min(iy, LT2 - 1 - iy), min(ix, LT2 - 1 - ix));
        }
        if (ok) {
            float xv = (dom && !zero) ? g_x[b * NN + gy * 127 + gx] : 0.0f;
            xs0[p] = xv;
            xs1[p] = xv;
            fs[p]  = dom ? f[b * NN + gy * 127 + gx] : 0.0f;
        }
        dk[k] = d;
    }
    __syncthreads();

    float* cur = xs0;
    float* nxt = xs1;
#pragma unroll
    for (int s = 0; s < 10; ++s) {
#pragma unroll
        for (int k = 0; k < 6; ++k) {
            if (s < dk[k]) {
                int p = tid + k * 512;
                float ax = k0 * cur[p - LT2 - 1] + k1 * cur[p - LT2] + k2 * cur[p - LT2 + 1]
                         + k3 * cur[p - 1]       + k4 * cur[p]       + k5 * cur[p + 1]
                         + k6 * cur[p + LT2 - 1] + k7 * cur[p + LT2] + k8 * cur[p + LT2 + 1];
                nxt[p] = cur[p] + tau * (fs[p] - ax);
            }
        }
        __syncthreads();
        float* tsw = cur; cur = nxt; nxt = tsw;
    }

#pragma unroll
    for (int k = 0; k < 2; ++k) {
        int p2 = tid + k * 512;
        int py = p2 >> 5, px = p2 & 31;
        int iy = HL2 + py, ix = HL2 + px;
        int gy = oy + iy, gx = ox + ix;
        if (((unsigned)gy < 127u) && ((unsigned)gx < 127u)) {
            int i = iy * LT2 + ix;
            g_x[b * NN + gy * 127 + gx] = cur[i];
            if (final_) {
                float ax = k0 * cur[i - LT2 - 1] + k1 * cur[i - LT2] + k2 * cur[i - LT2 + 1]
                         + k3 * cur[i - 1]       + k4 * cur[i]       + k5 * cur[i + 1]
                         + k6 * cur[i + LT2 - 1] + k7 * cur[i + LT2] + k8 * cur[i + LT2 + 1];
                g_r[b * NN + gy * 127 + gx] = fs[i] - ax;
            }
        }
    }
}

// ifft2 pass 1, packed: two real expanded rows per complex FFT.
__global__ void __launch_bounds__(256)
fft_row_expand(const int* __restrict__ ep, int iter) {
    if (iter >= get_K(ep)) return;
    __shared__ float2 s[4][256];
    __shared__ float2 tw[192];
    int b = blockIdx.y, t = threadIdx.x, ty = threadIdx.y;
    int j = blockIdx.x * 4 + ty;                // 0..63
    int y1 = 2 * j + 1;
    int y2 = 2 * j + 2;
    bool two = (j < 63);
    build_tw(tw, ty * 64 + t, 1.0f);
    const float* r1 = g_r + (b * NN + (y1 - 1) * 127);
    const float* r2 = g_r + (b * NN + (two ? (y2 - 1) : 0) * 127);
#pragma unroll
    for (int k = 0; k < 4; ++k) {
        int p = t + k * 64;
        float v1 = 0.0f, v2 = 0.0f;
        if (p >= 1 && p <= 127) {
            v1 = r1[p - 1];
            if (two) v2 = r2[p - 1];
        } else if (p >= 129) {
            v1 = -r1[255 - p];
            if (two) v2 = -r2[255 - p];
        }
        s[ty][dr4(p)] = make_float2(v1, v2);
    }
    __syncthreads();
    fft256_r4<1, 1>(s[ty], tw, t);
    float2* base = g_FA + (size_t)b * IMG;
#pragma unroll
    for (int k = 0; k < 2; ++k) {
        int kk = t + k * 64;
        float2 Zk = s[ty][kk];
        float2 Zm = s[ty][(256 - kk) & 255];
        float sr_ = Zk.x + Zm.x, si_ = Zk.y - Zm.y;
        float dr_ = Zk.x - Zm.x, di_ = Zk.y + Zm.y;
        float2 F1 = make_float2(0.5f * sr_, 0.5f * si_);
        float2 F2 = make_float2(0.5f * di_, -0.5f * dr_);
        base[y1 * 256 + kk]         = F1;
        base[(256 - y1) * 256 + kk] = make_float2(-F1.x, -F1.y);
        if (two) {
            base[y2 * 256 + kk]         = F2;
            base[(256 - y2) * 256 + kk] = make_float2(-F2.x, -F2.y);
        }
    }
    if (blockIdx.x == 0 && ty == 0) {
#pragma unroll
        for (int k = 0; k < 2; ++k) {
            int kk = t + k * 64;
            base[kk]             = make_float2(0.f, 0.f);
            base[128 * 256 + kk] = make_float2(0.f, 0.f);
        }
    }
}

// ifft2 pass 2: columns 0..127; output purely REAL into g_FB (float view).
__global__ void __launch_bounds__(1024)
fft_col_inv(const int* __restrict__ ep, int iter) {
    if (iter >= get_K(ep)) return;
    __shared__ float2 s[256 * 16];
    __shared__ float2 tw[192];
    int b  = blockIdx.y;
    int tx = threadIdx.x, ty = threadIdx.y;     // 16 x 64
    int tid = ty * 16 + tx;
    int x = blockIdx.x * 16 + tx;               // 0..127
    build_tw(tw, tid, 1.0f);
#pragma unroll
    for (int k = 0; k < 4; ++k) {
        int r = ty + k * 64;
        s[dr4(r) * 16 + tx] = g_FA[(b * 256 + r) * 256 + x];
    }
    __syncthreads();
    fft256_r4<16, 1>(s + tx, tw, ty);
    const float sc = 1.0f / 65536.0f;
    float* FB = (float*)g_FB;
#pragma unroll
    for (int k = 0; k < 4; ++k) {
        int r = ty + k * 64;
        float val = s[r * 16 + tx].x * sc;
        int n2 = (r ^ 128);
        float* row = FB + (size_t)b * IMG + n2 * 256;
        if (x == 0) {
            row[128] = val;
            row[0]   = 0.0f;
        } else {
            row[x + 128] = val;
            row[128 - x] = -val;
        }
    }
}

// Composed forward 7x7 correlation, real input, *theta, write g_FA.
__global__ void __launch_bounds__(256)
conv7(const float* __restrict__ inR, float2* __restrict__ out,
      const float* __restrict__ thr, const float* __restrict__ thi,
      const int* __restrict__ ep, int iter) {
    if (iter >= get_K(ep)) return;
    __shared__ float sr[38 * 38];
    __shared__ float Kr[49], Ki[49];
    int b  = blockIdx.z;
    int ox = blockIdx.x * 32;
    int oy = blockIdx.y * 32;
    int tid = threadIdx.x;

    if (tid < 49) {
        float2 w = g_Kc[b * 98 + tid];
        Kr[tid] = w.x;
        Ki[tid] = w.y;
    }
    for (int i = tid; i < 38 * 38; i += 256) {
        int iy = i / 38, ix = i - iy * 38;
        int gy = oy - 3 + iy, gx = ox - 3 + ix;
        bool in = ((unsigned)gy < 256u) && ((unsigned)gx < 256u);
        sr[i] = in ? inR[(size_t)b * IMG + gy * 256 + gx] : 0.0f;
    }
    __syncthreads();

    int py  = tid >> 3;
    int px0 = (tid & 7) * 4;
    int base = py * 38 + px0;

    float aR[4] = {0.f, 0.f, 0.f, 0.f};
    float aI[4] = {0.f, 0.f, 0.f, 0.f};

    for (int dy = 0; dy < 7; ++dy) {
        int rowo = base + dy * 38;
        float v[10];
#pragma unroll
        for (int j = 0; j < 10; ++j) v[j] = sr[rowo + j];
#pragma unroll
        for (int dx = 0; dx < 7; ++dx) {
            float wr = Kr[dy * 7 + dx];
            float wi = Ki[dy * 7 + dx];
#pragma unroll
            for (int k = 0; k < 4; ++k) {
                aR[k] = fmaf(v[dx + k], wr, aR[k]);
                aI[k] = fmaf(v[dx + k], wi, aI[k]);
            }
        }
    }

    int grow = (oy + py) * 256 + ox + px0;
#pragma unroll
    for (int k = 0; k < 4; ++k) {
        int gidx = grow + k;
        float rr = aR[k], ii = aI[k];
        float tr = thr[b * IMG + gidx], ti = thi[b * IMG + gidx];
        float nr = rr * tr - ii * ti;
        float ni = rr * ti + ii * tr;
        out[(size_t)b * IMG + gidx] = make_float2(nr, ni);
    }
}

// fft2 pass 1: ifftshift on read (from g_FA), forward FFT along x; write g_FB.
__global__ void __launch_bounds__(128)
fft_row_fwd(const int* __restrict__ ep, int iter) {
    if (iter >= get_K(ep)) return;
    __shared__ float2 s[2][256];
    __shared__ float2 tw[192];
    int b = blockIdx.y, t = threadIdx.x, ty = threadIdx.y;
    int y = blockIdx.x * 2 + ty;
    build_tw(tw, ty * 64 + t, -1.0f);
    build_tw(tw, 128 + ty * 64 + t, -1.0f);
    const float2* irow = g_FA + (b * 256 + (y ^ 128)) * 256;
#pragma unroll
    for (int k = 0; k < 4; ++k) {
        int p = t + k * 64;
        s[ty][dr4(p)] = irow[p ^ 128];
    }
    __syncthreads();
    fft256_r4<1, -1>(s[ty], tw, t);
    float2* orow = g_FB + (b * 256 + y) * 256;
    orow[t]      = s[ty][t];
    orow[t + 64] = s[ty][t + 64];
}

// fft2 pass 2: columns 0..127 (from g_FB), col FFT, multiply by Wa, accumulate.
__global__ void __launch_bounds__(1024)
fft_col_fwd_accum(const int* __restrict__ ep, int iter) {
    if (iter >= get_K(ep)) return;
    __shared__ float2 s[256 * 16];
    __shared__ float2 tw[192];
    int b  = blockIdx.y;
    int tx = threadIdx.x, ty = threadIdx.y;     // 16 x 64
    int tid = ty * 16 + tx;
    int x = blockIdx.x * 16 + tx;
    build_tw(tw, tid, -1.0f);
#pragma unroll
    for (int k = 0; k < 4; ++k) {
        int r = ty + k * 64;
        s[dr4(r) * 16 + tx] = g_FB[(b * 256 + r) * 256 + x];
    }
    __syncthreads();
    fft256_r4<16, -1>(s + tx, tw, ty);
    if (x < 127) {
#pragma unroll
        for (int k = 0; k < 4; ++k) {
            int r = ty + k * 64;
            if (r < 127) {
                float2 S = s[r * 16 + tx];
                float2 w = g_Wa[b * NN + r * 127 + x];
                g_x[b * NN + r * 127 + x] += w.x * S.x - w.y * S.y;
            }
        }
    }
}

// Residual norm.
__global__ void __launch_bounds__(256)
norm_partial(const float* __restrict__ f, const float* __restrict__ kA) {
    __shared__ float sr_s[256], sf_s[256];
    int b = blockIdx.y;
    int row = blockIdx.x * 2 + (threadIdx.x >> 7);
    int col = threadIdx.x & 127;
    float sr = 0.0f, sf = 0.0f;
    if (row < 127 && col < 127) {
        int p = row * 127 + col;
        const float* ka = kA + b * 9;
        const float* xb = g_x + b * NN;
        float s = 0.0f;
        if (row > 0) {
            if (col > 0)   s += ka[0] * xb[p - 128];
            s += ka[1] * xb[p - 127];
            if (col < 126) s += ka[2] * xb[p - 126];
        }
        if (col > 0)   s += ka[3] * xb[p - 1];
        s += ka[4] * xb[p];
        if (col < 126) s += ka[5] * xb[p + 1];
        if (row < 126) {
            if (col > 0)   s += ka[6] * xb[p + 126];
            s += ka[7] * xb[p + 127];
            if (col < 126) s += ka[8] * xb[p + 128];
        }
        float fv = f[b * NN + p];
        float rv = fv - s;
        sr = rv * rv;
        sf = fv * fv;
    }
    sr_s[threadIdx.x] = sr;
    sf_s[threadIdx.x] = sf;
    __syncthreads();
    for (int o = 128; o > 0; o >>= 1) {
        if (threadIdx.x < o) {
            sr_s[threadIdx.x] += sr_s[threadIdx.x + o];
            sf_s[threadIdx.x] += sf_s[threadIdx.x + o];
        }
        __syncthreads();
    }
    if (threadIdx.x == 0) g_part[b * 64 + blockIdx.x] = make_float2(sr_s[0], sf_s[0]);
}

__global__ void norm_final(float* __restrict__ out) {
    __shared__ float sr_s[256], sf_s[256];
    float sr = 0.0f, sf = 0.0f;
#pragma unroll
    for (int k = 0; k < 4; ++k) {
        float2 v = g_part[threadIdx.x + k * 256];
        sr += v.x; sf += v.y;
    }
    sr_s[threadIdx.x] = sr;
    sf_s[threadIdx.x] = sf;
    __syncthreads();
    for (int o = 128; o > 0; o >>= 1) {
        if (threadIdx.x < o) {
            sr_s[threadIdx.x] += sr_s[threadIdx.x + o];
            sf_s[threadIdx.x] += sf_s[threadIdx.x + o];
        }
        __syncthreads();
    }
    if (threadIdx.x == 0) out[0] = sqrtf(sr_s[0] / sf_s[0]);
}

// ---------------- launch ------------------------------------------------------
extern "C" void kernel_launch(void* const* d_in, const int* in_sizes, int n_in,
                              void* d_out, int out_size) {
    (void)in_sizes; (void)n_in; (void)out_size;
    const float* f   = (const float*)d_in[0];
    const float* kA  = (const float*)d_in[1];
    const float* w1r = (const float*)d_in[2];
    const float* w1i = (const float*)d_in[3];
    const float* w2r = (const float*)d_in[4];
    const float* w2i = (const float*)d_in[5];
    const float* w3r = (const float*)d_in[6];
    const float* w3i = (const float*)d_in[7];
    const float* thr = (const float*)d_in[8];
    const float* thi = (const float*)d_in[9];
    const int*   ep  = (const int*)d_in[10];
    float* out = (float*)d_out;

    void *pFA = nullptr, *pFB = nullptr;
    cudaGetSymbolAddress(&pFA, g_FA);
    cudaGetSymbolAddress(&pFB, g_FB);

    compose_kernels<<<NB, 64>>>(w1r, w1i, w2r, w2i, w3r, w3i);
    build_Wa<<<NB, 256>>>();

    dim3 jg(4, 4, NB);
    for (int it = 0; it < 3; ++it) {
        jacobi_tile<<<jg, 512>>>(f, kA, ep, it, 0, it == 0 ? 1 : 0);
        jacobi_tile<<<jg, 512>>>(f, kA, ep, it, 1, 0);
        fft_row_expand<<<dim3(16, NB), dim3(64, 4)>>>(ep, it);
        fft_col_inv<<<dim3(8, NB), dim3(16, 64)>>>(ep, it);
        conv7<<<dim3(8, 8, NB), 256>>>(
            (const float*)pFB, (float2*)pFA, thr, thi, ep, it);
        fft_row_fwd<<<dim3(128, NB), dim3(64, 2)>>>(ep, it);
        fft_col_fwd_accum<<<dim3(8, NB), dim3(16, 64)>>>(ep, it);
    }

    norm_partial<<<dim3(64, NB), 256>>>(f, kA);
    norm_final<<<1, 256>>>(out);
}